// round 14
// baseline (speedup 1.0000x reference)
#include <cuda_runtime.h>
#include <cuda_fp16.h>
#include <math.h>
#include <stdint.h>

#define N_NEWS  30000
#define N_INTER 60000
#define HID 128
#define NH  8
#define HD  16
#define E_NN_CAP 480000
#define E_IN_CAP 960000

// ---------------- scratch (static device globals; no allocation) ----------------
__device__ float    g_h_news [N_NEWS  * HID];
__device__ float    g_h_inter[N_INTER * HID];
__device__ uint32_t g_hh_news [N_NEWS  * 64];   // half2-packed h (for gather)
__device__ uint32_t g_hh_inter[N_INTER * 64];
__device__ float    g_out_nn [N_NEWS  * HID];
__device__ float    g_out_in [N_NEWS  * HID];
__device__ uint32_t g_BtNh   [HID * 384];       // W_news^T, half2-packed [n][k/2]
__device__ uint32_t g_BtIh   [HID * 384];       // W_inter^T, half2-packed
__device__ float    g_BtK    [HID * HID];       // Wk^T, tf32-rounded bits
__device__ float    g_asrc_nn[N_NEWS  * NH];
__device__ float    g_adst_nn[N_NEWS  * NH];
__device__ float    g_asrc_in[N_INTER * NH];
__device__ float    g_adst_in[N_NEWS  * NH];
__device__ int      g_deg_nn [N_NEWS];
__device__ int      g_deg_in [N_NEWS];
__device__ int      g_rp_nn  [N_NEWS + 1];
__device__ int      g_rp_in  [N_NEWS + 1];
__device__ int      g_cur_nn [N_NEWS];
__device__ int      g_cur_in [N_NEWS];
__device__ int      g_csr_nn [E_NN_CAP];
__device__ int      g_csr_in [E_IN_CAP];
__device__ float    g_accsem[2 * HID];
__device__ float    g_beta  [2];

// ---------------- helpers ----------------
static __device__ __forceinline__ uint32_t smem_u32(const void* p) {
    uint32_t r;
    asm("{ .reg .u64 t; cvta.to.shared.u64 t, %1; cvt.u32.u64 %0, t; }" : "=r"(r) : "l"(p));
    return r;
}
static __device__ __forceinline__ uint32_t f2tf(float x) {
    uint32_t r;
    asm("cvt.rna.tf32.f32 %0, %1;" : "=r"(r) : "f"(x));
    return r;
}
static __device__ __forceinline__ void mma_tf32(float* c, const uint32_t* a, const uint32_t* b) {
    asm volatile(
        "mma.sync.aligned.m16n8k8.row.col.f32.tf32.tf32.f32 "
        "{%0,%1,%2,%3},{%4,%5,%6,%7},{%8,%9},{%0,%1,%2,%3};"
        : "+f"(c[0]), "+f"(c[1]), "+f"(c[2]), "+f"(c[3])
        : "r"(a[0]), "r"(a[1]), "r"(a[2]), "r"(a[3]), "r"(b[0]), "r"(b[1]));
}
static __device__ __forceinline__ void mma_f16(float* c, const uint32_t* a, const uint32_t* b) {
    asm volatile(
        "mma.sync.aligned.m16n8k16.row.col.f32.f16.f16.f32 "
        "{%0,%1,%2,%3},{%4,%5,%6,%7},{%8,%9},{%0,%1,%2,%3};"
        : "+f"(c[0]), "+f"(c[1]), "+f"(c[2]), "+f"(c[3])
        : "r"(a[0]), "r"(a[1]), "r"(a[2]), "r"(a[3]), "r"(b[0]), "r"(b[1]));
}
static __device__ __forceinline__ void cp16(uint32_t dst, const void* src) {
    asm volatile("cp.async.cg.shared.global [%0], [%1], 16;" :: "r"(dst), "l"(src));
}
static __device__ __forceinline__ void ldsm4(uint32_t* r, uint32_t addr) {
    asm volatile("ldmatrix.sync.aligned.m8n8.x4.shared.b16 {%0,%1,%2,%3}, [%4];"
                 : "=r"(r[0]), "=r"(r[1]), "=r"(r[2]), "=r"(r[3]) : "r"(addr));
}
__device__ __forceinline__ float lrelu02(float x) { return x > 0.f ? x : 0.2f * x; }
static __device__ __forceinline__ uint32_t pack_h2(float a, float b) {
    __half2 h = __floats2half2_rn(a, b);
    return *reinterpret_cast<uint32_t*>(&h);
}

// ---------------- setup: zero degree counters ----------------
__global__ void zero_deg2(int* __restrict__ d1, int* __restrict__ d2, int n) {
    int i = blockIdx.x * blockDim.x + threadIdx.x;
    if (i < n) { d1[i] = 0; d2[i] = 0; }
}

// ---------------- weight prep: fp16-pack projection weights, tf32 Wk, zero accsem ----------------
__global__ void transpose_all(const float* __restrict__ Wn, const float* __restrict__ Wi,
                              const float* __restrict__ Wk,
                              uint32_t* __restrict__ BtNh, uint32_t* __restrict__ BtIh,
                              float* __restrict__ BtK, float* __restrict__ accsem)
{
    int i = blockIdx.x * blockDim.x + threadIdx.x;
    if (i < 128 * 384) {                 // (n, k-pair)
        int n = i / 384, kp = i % 384;
        BtNh[i] = pack_h2(Wn[(2 * kp) * 128 + n], Wn[(2 * kp + 1) * 128 + n]);
        BtIh[i] = pack_h2(Wi[(2 * kp) * 128 + n], Wi[(2 * kp + 1) * 128 + n]);
    }
    if (i < 128 * 128) {
        int n = i >> 7, k = i & 127;
        BtK[i] = __uint_as_float(f2tf(Wk[k * 128 + n]));
    }
    if (i < 2 * HID) accsem[i] = 0.f;
}

#define LDT 36              // padded row length (32-bit words); 144B rows
#define BUF_F (128 * LDT)   // words per (A or B) tile

// ---------------- fp16 tensor-core GEMM (projection, dual-part, 2-stage, A dist-2 prefetch) ----------------
__global__ __launch_bounds__(256, 2)
void mma_gemm_h(const float* __restrict__ A1, const float* __restrict__ A2,
                const uint32_t* __restrict__ Bt1, const uint32_t* __restrict__ Bt2,
                const float* __restrict__ bias1, const float* __restrict__ bias2,
                float* __restrict__ C1, float* __restrict__ C2,
                uint32_t* __restrict__ Hh1, uint32_t* __restrict__ Hh2,
                int M1, int M2, int nb1, int K)
{
    extern __shared__ uint32_t smw[];   // [2][A + B] tiles (words)
    __shared__ float s_bias[128];

    const int tid  = threadIdx.x;
    const int warp = tid >> 5;
    const int lane = tid & 31;
    const int group = lane >> 2, tig = lane & 3;
    const int warpM = warp & 3, warpN = warp >> 2;
    const int mbase = warpM * 32, nbase = warpN * 64;

    const float* A; const uint32_t* Bt; const float* bias; float* C; uint32_t* Hh; int M, m0;
    if ((int)blockIdx.x < nb1) {
        A = A1; Bt = Bt1; bias = bias1; C = C1; Hh = Hh1; M = M1; m0 = blockIdx.x * 128;
    } else {
        A = A2; Bt = Bt2; bias = bias2; C = C2; Hh = Hh2; M = M2; m0 = (blockIdx.x - nb1) * 128;
    }
    const int Kw = K >> 1;              // B row length in words

    if (tid < 128) s_bias[tid] = bias[tid];

    float acc[2][8][4];
#pragma unroll
    for (int i = 0; i < 2; i++)
#pragma unroll
        for (int j = 0; j < 8; j++)
#pragma unroll
            for (int l = 0; l < 4; l++) acc[i][j][l] = 0.f;

    const int nchunk = K >> 6;          // 64 halfs per chunk (12 for K=768)
    const uint32_t smem_b = smem_u32(smw);

    const int rowL = tid >> 3, qL = tid & 7;
    const int blk = lane >> 3, rr = lane & 7;
    const uint32_t offA = (uint32_t)(((mbase + (blk & 1) * 8 + rr) * LDT + (blk >> 1) * 4) * 4);
    const uint32_t offB = (uint32_t)(((nbase + (blk >> 1) * 8 + rr) * LDT + (blk & 1) * 4) * 4);

    // double register A-prefetch buffers (distance-2)
    uint4 pa[2][4];
    auto prefetchA = [&](int c, uint4* dst) {
        const int kb = c * 64;
#pragma unroll
        for (int p = 0; p < 4; p++) {
            int row = rowL + 32 * p;
            int m = m0 + row;
            if (m < M) {
                const float4* src = reinterpret_cast<const float4*>(A + (size_t)m * K + kb + qL * 8);
                float4 va = src[0], vb = src[1];
                dst[p] = make_uint4(pack_h2(va.x, va.y), pack_h2(va.z, va.w),
                                    pack_h2(vb.x, vb.y), pack_h2(vb.z, vb.w));
            } else {
                dst[p] = make_uint4(0u, 0u, 0u, 0u);
            }
        }
    };
    auto issueB = [&](int c) {
        const int kbw = c * 32;
        const uint32_t bo = smem_b + ((uint32_t)(((c & 1) * 2 + 1) * BUF_F) << 2);
#pragma unroll
        for (int p = 0; p < 4; p++) {
            int row = rowL + 32 * p;
            cp16(bo + (uint32_t)((row * LDT + qL * 4) << 2),
                 Bt + (size_t)row * Kw + kbw + qL * 4);
        }
        asm volatile("cp.async.commit_group;");
    };

    prefetchA(0, pa[0]);
    prefetchA(1, pa[1]);                // nchunk >= 2 always (K=768)
    issueB(0);

    for (int c = 0; c < nchunk; c++) {
        // store A(c) into smem buf c&1; its register buffer is then reissued for c+2
        uint32_t* Asm = smw + (c & 1) * 2 * BUF_F;
#pragma unroll
        for (int p = 0; p < 4; p++) {
            int row = rowL + 32 * p;
            *reinterpret_cast<uint4*>(Asm + row * LDT + qL * 4) = pa[c & 1][p];
        }
        if (c + 2 < nchunk) prefetchA(c + 2, pa[c & 1]);   // ~2 chunk-phases of cover
        if (c + 1 < nchunk) {
            issueB(c + 1);
            asm volatile("cp.async.wait_group 1;");
        } else {
            asm volatile("cp.async.wait_group 0;");
        }
        __syncthreads();

        const uint32_t Asb = smem_b + ((uint32_t)((c & 1) * 2 * BUF_F) << 2);
        const uint32_t Bsb = Asb + (uint32_t)(BUF_F << 2);
#pragma unroll
        for (int ks = 0; ks < 4; ks++) {           // 4 x k16 steps (32B each)
            uint32_t af[2][4], bf[8][2];
            ldsm4(af[0], Asb + offA + (uint32_t)(ks * 32));
            ldsm4(af[1], Asb + offA + (uint32_t)(16 * LDT * 4 + ks * 32));
#pragma unroll
            for (int na2 = 0; na2 < 8; na2 += 2) {
                uint32_t t[4];
                ldsm4(t, Bsb + offB + (uint32_t)(na2 * 8 * LDT * 4 + ks * 32));
                bf[na2][0] = t[0]; bf[na2][1] = t[1];
                bf[na2 + 1][0] = t[2]; bf[na2 + 1][1] = t[3];
            }
#pragma unroll
            for (int ma = 0; ma < 2; ma++)
#pragma unroll
                for (int na = 0; na < 8; na++)
                    mma_f16(acc[ma][na], af[ma], bf[na]);
        }
        __syncthreads();
    }

    // -------- epilogue: bias + fp32 store + half2 pack --------
#pragma unroll
    for (int ma = 0; ma < 2; ma++) {
        int row = m0 + mbase + ma * 16 + group;
#pragma unroll
        for (int na = 0; na < 8; na++) {
            int col = nbase + na * 8 + tig * 2;
            if (row < M) {
                float2 v = { acc[ma][na][0] + s_bias[col],
                             acc[ma][na][1] + s_bias[col + 1] };
                *reinterpret_cast<float2*>(C + (size_t)row * 128 + col) = v;
                Hh[(size_t)row * 64 + (col >> 1)] = pack_h2(v.x, v.y);
            }
            if (row + 8 < M) {
                float2 v = { acc[ma][na][2] + s_bias[col],
                             acc[ma][na][3] + s_bias[col + 1] };
                *reinterpret_cast<float2*>(C + (size_t)(row + 8) * 128 + col) = v;
                Hh[(size_t)(row + 8) * 64 + (col >> 1)] = pack_h2(v.x, v.y);
            }
        }
    }
}

// ---------------- tf32 tensor-core GEMM (semantic only, dual-part, 2-stage) ----------------
__global__ __launch_bounds__(256, 2)
void mma_gemm(const float* __restrict__ A1, const float* __restrict__ A2,
              const float* __restrict__ Bt1, const float* __restrict__ Bt2,
              const float* __restrict__ bias1, const float* __restrict__ bias2,
              float* __restrict__ C1, float* __restrict__ C2,
              int M1, int M2, int nb1, int K)
{
    extern __shared__ float smem[];     // [2][A + B] tiles
    __shared__ float s_bias[128];
    __shared__ float s_col[128];

    const int tid  = threadIdx.x;
    const int warp = tid >> 5;
    const int lane = tid & 31;
    const int group = lane >> 2, tig = lane & 3;
    const int warpM = warp & 3, warpN = warp >> 2;
    const int mbase = warpM * 32, nbase = warpN * 64;

    const float* A; const float* Bt; const float* bias; float* C; int M, m0;
    if ((int)blockIdx.x < nb1) {
        A = A1; Bt = Bt1; bias = bias1; C = C1; M = M1; m0 = blockIdx.x * 128;
    } else {
        A = A2; Bt = Bt2; bias = bias2; C = C2; M = M2; m0 = (blockIdx.x - nb1) * 128;
    }

    if (tid < 128) { s_bias[tid] = bias[tid]; s_col[tid] = 0.f; }

    float acc[2][8][4];
#pragma unroll
    for (int i = 0; i < 2; i++)
#pragma unroll
        for (int j = 0; j < 8; j++)
#pragma unroll
            for (int l = 0; l < 4; l++) acc[i][j][l] = 0.f;

    const int nchunk = K >> 5;
    const uint32_t smem_b = smem_u32(smem);

    const int rowL = tid >> 3, qL = tid & 7;
    const int blk = lane >> 3, rr = lane & 7;
    const uint32_t offA = (uint32_t)(((mbase + (blk & 1) * 8 + rr) * LDT + (blk >> 1) * 4) * 4);
    const uint32_t offB = (uint32_t)(((nbase + (blk >> 1) * 8 + rr) * LDT + (blk & 1) * 4) * 4);

    float4 pA[4];
#pragma unroll
    for (int l = 0; l < 4; l++) {
        int m = m0 + rowL + 32 * l;
        pA[l] = (m < M) ? *reinterpret_cast<const float4*>(A + (size_t)m * K + qL * 4)
                        : make_float4(0.f, 0.f, 0.f, 0.f);
    }
#pragma unroll
    for (int l = 0; l < 4; l++) {
        int row = rowL + 32 * l;
        cp16(smem_b + (uint32_t)((BUF_F + row * LDT + qL * 4) << 2),
             Bt + (size_t)row * K + qL * 4);
    }
    asm volatile("cp.async.commit_group;");

    for (int c = 0; c < nchunk; c++) {
#pragma unroll
        for (int l = 0; l < 4; l++) {
            int row = rowL + 32 * l;
            float4 v = pA[l];
            float4 u = make_float4(__uint_as_float(f2tf(v.x)), __uint_as_float(f2tf(v.y)),
                                   __uint_as_float(f2tf(v.z)), __uint_as_float(f2tf(v.w)));
            *reinterpret_cast<float4*>(smem + (c & 1) * 2 * BUF_F + row * LDT + qL * 4) = u;
        }
        if (c + 1 < nchunk) {
            const int kb = (c + 1) * 32;
            const uint32_t bufo2 = (uint32_t)(((c + 1) & 1) * 2 * BUF_F) << 2;
#pragma unroll
            for (int l = 0; l < 4; l++) {
                int row = rowL + 32 * l;
                cp16(smem_b + bufo2 + (uint32_t)((BUF_F + row * LDT + qL * 4) << 2),
                     Bt + (size_t)row * K + kb + qL * 4);
            }
            asm volatile("cp.async.commit_group;");
            asm volatile("cp.async.wait_group 1;");
        } else {
            asm volatile("cp.async.wait_group 0;");
        }
        __syncthreads();
        if (c + 1 < nchunk) {
            const int kb = (c + 1) * 32;
#pragma unroll
            for (int l = 0; l < 4; l++) {
                int m = m0 + rowL + 32 * l;
                pA[l] = (m < M) ? *reinterpret_cast<const float4*>(A + (size_t)m * K + kb + qL * 4)
                                : make_float4(0.f, 0.f, 0.f, 0.f);
            }
        }
        const uint32_t Asb = smem_b + ((uint32_t)((c & 1) * 2 * BUF_F) << 2);
        const uint32_t Bsb = Asb + (uint32_t)(BUF_F << 2);
#pragma unroll
        for (int ks = 0; ks < 4; ks++) {
            uint32_t af[2][4], bf[8][2];
            ldsm4(af[0], Asb + offA + (uint32_t)((ks * 8) << 2));
            ldsm4(af[1], Asb + offA + (uint32_t)((16 * LDT + ks * 8) << 2));
#pragma unroll
            for (int na2 = 0; na2 < 8; na2 += 2) {
                uint32_t t[4];
                ldsm4(t, Bsb + offB + (uint32_t)((na2 * 8 * LDT + ks * 8) << 2));
                bf[na2][0] = t[0]; bf[na2][1] = t[1];
                bf[na2 + 1][0] = t[2]; bf[na2 + 1][1] = t[3];
            }
#pragma unroll
            for (int ma = 0; ma < 2; ma++)
#pragma unroll
                for (int na = 0; na < 8; na++)
                    mma_tf32(acc[ma][na], af[ma], bf[na]);
        }
        __syncthreads();
    }

    // semantic epilogue: column sums of tanh(acc + bias)
#pragma unroll
    for (int na = 0; na < 8; na++) {
        int col = nbase + na * 8 + tig * 2;
        float p0 = 0.f, p1 = 0.f;
#pragma unroll
        for (int ma = 0; ma < 2; ma++) {
            int row = m0 + mbase + ma * 16 + group;
            if (row < M) {
                p0 += tanhf(acc[ma][na][0] + s_bias[col]);
                p1 += tanhf(acc[ma][na][1] + s_bias[col + 1]);
            }
            if (row + 8 < M) {
                p0 += tanhf(acc[ma][na][2] + s_bias[col]);
                p1 += tanhf(acc[ma][na][3] + s_bias[col + 1]);
            }
        }
        atomicAdd(&s_col[col], p0);
        atomicAdd(&s_col[col + 1], p1);
    }
    __syncthreads();
    if (tid < 128) atomicAdd(&C[tid], s_col[tid]);
}

// ---------------- attention dots, both node types in one launch ----------------
__global__ void att_all(const float* __restrict__ hN, const float* __restrict__ hI,
                        const float* __restrict__ v0, const float* __restrict__ v1,
                        const float* __restrict__ v2, const float* __restrict__ v3,
                        float* __restrict__ o0, float* __restrict__ o1,
                        float* __restrict__ o2, float* __restrict__ o3, int nbA)
{
    __shared__ float sv[4][128];
    if (threadIdx.x < 128) {
        sv[0][threadIdx.x] = v0[threadIdx.x];
        sv[1][threadIdx.x] = v1[threadIdx.x];
        sv[2][threadIdx.x] = v2[threadIdx.x];
        sv[3][threadIdx.x] = v3[threadIdx.x];
    }
    __syncthreads();
    if ((int)blockIdx.x < nbA) {
        int i = blockIdx.x * blockDim.x + threadIdx.x;
        if (i < N_NEWS * NH) {
            int n = i >> 3, hh = i & 7;
            const float* hp = hN + (size_t)n * HID + hh * HD;
            float s0 = 0.f, s1 = 0.f, s2 = 0.f;
#pragma unroll
            for (int d = 0; d < HD; d++) {
                float x = hp[d];
                s0 += x * sv[0][hh * HD + d];
                s1 += x * sv[1][hh * HD + d];
                s2 += x * sv[2][hh * HD + d];
            }
            o0[i] = s0; o1[i] = s1; o2[i] = s2;
        }
    } else {
        int i = (blockIdx.x - nbA) * blockDim.x + threadIdx.x;
        if (i < N_INTER * NH) {
            int n = i >> 3, hh = i & 7;
            const float* hp = hI + (size_t)n * HID + hh * HD;
            float s = 0.f;
#pragma unroll
            for (int d = 0; d < HD; d++) s += hp[d] * sv[3][hh * HD + d];
            o3[i] = s;
        }
    }
}

// ---------------- CSR build (merged dual-edge-type kernels) ----------------
__global__ void hist2(const int* __restrict__ e1, int E1, int* __restrict__ d1,
                      const int* __restrict__ e2, int E2, int* __restrict__ d2, int nb1)
{
    if ((int)blockIdx.x < nb1) {
        int e = blockIdx.x * blockDim.x + threadIdx.x;
        if (e < E1) atomicAdd(&d1[e1[E1 + e]], 1);
    } else {
        int e = (blockIdx.x - nb1) * blockDim.x + threadIdx.x;
        if (e < E2) atomicAdd(&d2[e2[E2 + e]], 1);
    }
}

__global__ __launch_bounds__(1024)
void scan2(const int* __restrict__ degA, int* __restrict__ rpA, int* __restrict__ curA,
           const int* __restrict__ degB, int* __restrict__ rpB, int* __restrict__ curB,
           int n)
{
    extern __shared__ int sdeg[];
    __shared__ int wsum[32];
    const int* deg = blockIdx.x ? degB : degA;
    int* rowptr    = blockIdx.x ? rpB  : rpA;
    int* cursor    = blockIdx.x ? curB : curA;

    const int t = threadIdx.x, lane = t & 31, wid = t >> 5;
    const int chunk = (n + 1023) >> 10;
    const int b = t * chunk;

    for (int i = t; i < n; i += 1024) sdeg[i] = deg[i];
    __syncthreads();

    int v[32];
    int sum = 0;
#pragma unroll
    for (int i = 0; i < 32; i++) {
        if (i < chunk) {
            int idx = b + i;
            int x = (idx < n) ? sdeg[idx] : 0;
            v[i] = sum;
            sum += x;
        }
    }
    int inc = sum;
#pragma unroll
    for (int off = 1; off < 32; off <<= 1) {
        int y = __shfl_up_sync(0xffffffffu, inc, off);
        if (lane >= off) inc += y;
    }
    if (lane == 31) wsum[wid] = inc;
    __syncthreads();
    if (wid == 0) {
        int ws = wsum[lane];
        int winc = ws;
#pragma unroll
        for (int off = 1; off < 32; off <<= 1) {
            int y = __shfl_up_sync(0xffffffffu, winc, off);
            if (lane >= off) winc += y;
        }
        wsum[lane] = winc - ws;
    }
    __syncthreads();
    const int base = wsum[wid] + (inc - sum);
#pragma unroll
    for (int i = 0; i < 32; i++) {
        if (i < chunk) {
            int idx = b + i;
            if (idx < n) sdeg[idx] = base + v[i];
        }
    }
    __syncthreads();
    for (int i = t; i < n; i += 1024) {
        int val = sdeg[i];
        rowptr[i] = val;
        cursor[i] = val;
    }
    if (t == 1023) rowptr[n] = base + sum;
}

__global__ void scatter2(const int* __restrict__ e1, int E1, int* __restrict__ c1, int* __restrict__ s1,
                         const int* __restrict__ e2, int E2, int* __restrict__ c2, int* __restrict__ s2,
                         int nb1)
{
    if ((int)blockIdx.x < nb1) {
        int e = blockIdx.x * blockDim.x + threadIdx.x;
        if (e < E1) { int pos = atomicAdd(&c1[e1[E1 + e]], 1); s1[pos] = e1[e]; }
    } else {
        int e = (blockIdx.x - nb1) * blockDim.x + threadIdx.x;
        if (e < E2) { int pos = atomicAdd(&c2[e2[E2 + e]], 1); s2[pos] = e2[e]; }
    }
}

// ---------------- fused single-pass softmax-aggregation: warp per dst node ----------------
__global__ __launch_bounds__(256)
void han_agg2(const int* __restrict__ rp1, const int* __restrict__ csr1,
              const float* __restrict__ as1, const float* __restrict__ ad1,
              const uint32_t* __restrict__ hh1, float* __restrict__ o1,
              const int* __restrict__ rp2, const int* __restrict__ csr2,
              const float* __restrict__ as2, const float* __restrict__ ad2,
              const uint32_t* __restrict__ hh2, float* __restrict__ o2)
{
    int gtid = blockIdx.x * blockDim.x + threadIdx.x;
    int w = gtid >> 5;
    int lane = threadIdx.x & 31;

    const int* rowptr; const int* csr; const float* asrc; const float* adst;
    const uint32_t* hh; float* out; int d;
    if (w < N_NEWS) {
        d = w; rowptr = rp1; csr = csr1; asrc = as1; adst = ad1; hh = hh1; out = o1;
    } else if (w < 2 * N_NEWS) {
        d = w - N_NEWS; rowptr = rp2; csr = csr2; asrc = as2; adst = ad2; hh = hh2; out = o2;
    } else return;

    const int beg = rowptr[d], end = rowptr[d + 1];
    const int deg = end - beg;
    float4* o = reinterpret_cast<float4*>(out) + (size_t)d * 32 + lane;
    if (deg == 0) { *o = make_float4(0.f, 0.f, 0.f, 0.f); return; }

    const int hdid = lane >> 2;
    const float adh = adst[(size_t)d * 8 + hdid];
    const uint2* h2p = reinterpret_cast<const uint2*>(hh);

    float den = 0.f, a0 = 0.f, a1 = 0.f, a2 = 0.f, a3 = 0.f;
    int i = 0;
    for (; i + 4 <= deg; i += 4) {
        int sA = csr[beg + i],     sB = csr[beg + i + 1];
        int sC = csr[beg + i + 2], sD = csr[beg + i + 3];
        float avA = asrc[(size_t)sA * 8 + hdid];
        float avB = asrc[(size_t)sB * 8 + hdid];
        float avC = asrc[(size_t)sC * 8 + hdid];
        float avD = asrc[(size_t)sD * 8 + hdid];
        uint2 gA = h2p[(size_t)sA * 32 + lane];
        uint2 gB = h2p[(size_t)sB * 32 + lane];
        uint2 gC = h2p[(size_t)sC * 32 + lane];
        uint2 gD = h2p[(size_t)sD * 32 + lane];
        float wA = __expf(lrelu02(avA + adh));
        float wB = __expf(lrelu02(avB + adh));
        float wC = __expf(lrelu02(avC + adh));
        float wD = __expf(lrelu02(avD + adh));
        den += (wA + wB) + (wC + wD);
        float2 lA0 = __half22float2(*reinterpret_cast<__half2*>(&gA.x));
        float2 lA1 = __half22float2(*reinterpret_cast<__half2*>(&gA.y));
        float2 lB0 = __half22float2(*reinterpret_cast<__half2*>(&gB.x));
        float2 lB1 = __half22float2(*reinterpret_cast<__half2*>(&gB.y));
        float2 lC0 = __half22float2(*reinterpret_cast<__half2*>(&gC.x));
        float2 lC1 = __half22float2(*reinterpret_cast<__half2*>(&gC.y));
        float2 lD0 = __half22float2(*reinterpret_cast<__half2*>(&gD.x));
        float2 lD1 = __half22float2(*reinterpret_cast<__half2*>(&gD.y));
        a0 += lA0.x * wA + lB0.x * wB + lC0.x * wC + lD0.x * wD;
        a1 += lA0.y * wA + lB0.y * wB + lC0.y * wC + lD0.y * wD;
        a2 += lA1.x * wA + lB1.x * wB + lC1.x * wC + lD1.x * wD;
        a3 += lA1.y * wA + lB1.y * wB + lC1.y * wC + lD1.y * wD;
    }
    for (; i < deg; i++) {
        int s = csr[beg + i];
        float av = asrc[(size_t)s * 8 + hdid];
        uint2 g = h2p[(size_t)s * 32 + lane];
        float wgt = __expf(lrelu02(av + adh));
        den += wgt;
        float2 l0 = __half22float2(*reinterpret_cast<__half2*>(&g.x));
        float2 l1 = __half22float2(*reinterpret_cast<__half2*>(&g.y));
        a0 += l0.x * wgt; a1 += l0.y * wgt;
        a2 += l1.x * wgt; a3 += l1.y * wgt;
    }
    float invd = 1.f / (den + 1e-16f);
    *o = make_float4(fmaxf(a0 * invd, 0.f), fmaxf(a1 * invd, 0.f),
                     fmaxf(a2 * invd, 0.f), fmaxf(a3 * invd, 0.f));
}

// ---------------- semantic softmax beta ----------------
__global__ void beta_kernel(const float* __restrict__ acc, const float* __restrict__ q,
                            float* __restrict__ beta)
{
    __shared__ float red[2][4];
    int t = threadIdx.x;  // 128 threads
    float s0 = q[t] * acc[t]       * (1.f / N_NEWS);
    float s1 = q[t] * acc[128 + t] * (1.f / N_NEWS);
#pragma unroll
    for (int off = 16; off; off >>= 1) {
        s0 += __shfl_down_sync(0xffffffffu, s0, off);
        s1 += __shfl_down_sync(0xffffffffu, s1, off);
    }
    if ((t & 31) == 0) { red[0][t >> 5] = s0; red[1][t >> 5] = s1; }
    __syncthreads();
    if (t == 0) {
        float sc0 = red[0][0] + red[0][1] + red[0][2] + red[0][3];
        float sc1 = red[1][0] + red[1][1] + red[1][2] + red[1][3];
        float mx = fmaxf(sc0, sc1);
        float e0 = __expf(sc0 - mx), e1 = __expf(sc1 - mx);
        float inv = 1.f / (e0 + e1);
        beta[0] = e0 * inv;
        beta[1] = e1 * inv;
    }
}

// ---------------- final: fuse + ELU + [128x4] head (warp per node) ----------------
__global__ void final_kernel(const float* __restrict__ onn, const float* __restrict__ oin,
                             const float* __restrict__ beta, const float* __restrict__ Wout,
                             const float* __restrict__ bout, float* __restrict__ y)
{
    __shared__ float sw[HID * 4];
    for (int i = threadIdx.x; i < HID * 4; i += blockDim.x) sw[i] = Wout[i];
    __syncthreads();

    int gtid = blockIdx.x * blockDim.x + threadIdx.x;
    int node = gtid >> 5;
    int lane = threadIdx.x & 31;
    if (node >= N_NEWS) return;

    float b0 = beta[0], b1 = beta[1];
    float4 a = reinterpret_cast<const float4*>(onn)[(size_t)node * 32 + lane];
    float4 b = reinterpret_cast<const float4*>(oin)[(size_t)node * 32 + lane];
    float f[4] = { b0 * a.x + b1 * b.x, b0 * a.y + b1 * b.y,
                   b0 * a.z + b1 * b.z, b0 * a.w + b1 * b.w };
#pragma unroll
    for (int u = 0; u < 4; u++) f[u] = f[u] > 0.f ? f[u] : (__expf(f[u]) - 1.f);

    float p[4] = { 0.f, 0.f, 0.f, 0.f };
#pragma unroll
    for (int u = 0; u < 4; u++) {
        int r = lane * 4 + u;
#pragma unroll
        for (int c = 0; c < 4; c++) p[c] += f[u] * sw[r * 4 + c];
    }
#pragma unroll
    for (int off = 16; off; off >>= 1)
#pragma unroll
        for (int c = 0; c < 4; c++) p[c] += __shfl_down_sync(0xffffffffu, p[c], off);
    if (lane == 0) {
#pragma unroll
        for (int c = 0; c < 4; c++) y[(size_t)node * 4 + c] = p[c] + bout[c];
    }
}

// ---------------- host ----------------
static inline int cdiv(int a, int b) { return (a + b - 1) / b; }

extern "C" void kernel_launch(void* const* d_in, const int* in_sizes, int n_in,
                              void* d_out, int out_size)
{
    const float* x_news   = (const float*)d_in[0];
    const float* x_inter  = (const float*)d_in[1];
    const int*   edge_nn  = (const int*)  d_in[2];
    const int*   edge_in  = (const int*)  d_in[3];
    const float* W_news   = (const float*)d_in[4];
    const float* b_news   = (const float*)d_in[5];
    const float* W_inter  = (const float*)d_in[6];
    const float* b_inter  = (const float*)d_in[7];
    const float* a_src_nn = (const float*)d_in[8];
    const float* a_dst_nn = (const float*)d_in[9];
    const float* a_src_in = (const float*)d_in[10];
    const float* a_dst_in = (const float*)d_in[11];
    const float* Wk       = (const float*)d_in[12];
    const float* bk       = (const float*)d_in[13];
    const float* q        = (const float*)d_in[14];
    const float* W_out    = (const float*)d_in[15];
    const float* b_out    = (const float*)d_in[16];
    float* y = (float*)d_out;

    const int E_nn = in_sizes[2] / 2;
    const int E_in = in_sizes[3] / 2;

    float *h_news, *h_inter, *out_nn, *out_in, *BtK;
    float *asrc_nn, *adst_nn, *asrc_in, *adst_in, *accsem, *beta;
    uint32_t *hh_news, *hh_inter, *BtNh, *BtIh;
    int *deg_nn, *deg_in, *rp_nn, *rp_in, *cur_nn, *cur_in, *csr_nn, *csr_in;
    cudaGetSymbolAddress((void**)&h_news,  g_h_news);
    cudaGetSymbolAddress((void**)&h_inter, g_h_inter);
    cudaGetSymbolAddress((void**)&hh_news, g_hh_news);
    cudaGetSymbolAddress((void**)&hh_inter,g_hh_inter);
    cudaGetSymbolAddress((void**)&out_nn,  g_out_nn);
    cudaGetSymbolAddress((void**)&out_in,  g_out_in);
    cudaGetSymbolAddress((void**)&BtNh,    g_BtNh);
    cudaGetSymbolAddress((void**)&BtIh,    g_BtIh);
    cudaGetSymbolAddress((void**)&BtK,     g_BtK);
    cudaGetSymbolAddress((void**)&asrc_nn, g_asrc_nn);
    cudaGetSymbolAddress((void**)&adst_nn, g_adst_nn);
    cudaGetSymbolAddress((void**)&asrc_in, g_asrc_in);
    cudaGetSymbolAddress((void**)&adst_in, g_adst_in);
    cudaGetSymbolAddress((void**)&deg_nn,  g_deg_nn);
    cudaGetSymbolAddress((void**)&deg_in,  g_deg_in);
    cudaGetSymbolAddress((void**)&rp_nn,   g_rp_nn);
    cudaGetSymbolAddress((void**)&rp_in,   g_rp_in);
    cudaGetSymbolAddress((void**)&cur_nn,  g_cur_nn);
    cudaGetSymbolAddress((void**)&cur_in,  g_cur_in);
    cudaGetSymbolAddress((void**)&csr_nn,  g_csr_nn);
    cudaGetSymbolAddress((void**)&csr_in,  g_csr_in);
    cudaGetSymbolAddress((void**)&accsem,  g_accsem);
    cudaGetSymbolAddress((void**)&beta,    g_beta);

    // lazy one-time side stream + fork/join events
    static cudaStream_t s_side = nullptr;
    static cudaEvent_t  s_fork = nullptr, s_join = nullptr;
    if (!s_side) {
        cudaStreamCreateWithFlags(&s_side, cudaStreamNonBlocking);
        cudaEventCreateWithFlags(&s_fork, cudaEventDisableTiming);
        cudaEventCreateWithFlags(&s_join, cudaEventDisableTiming);
    }

    const int T = 256;
    const int SMEM_GEMM = 2 * 2 * BUF_F * 4;   // 73728 bytes (2 CTA/SM)
    const int SMEM_SCAN = N_NEWS * 4;          // 120000 bytes
    cudaFuncSetAttribute(mma_gemm, cudaFuncAttributeMaxDynamicSharedMemorySize, SMEM_GEMM);
    cudaFuncSetAttribute(mma_gemm_h, cudaFuncAttributeMaxDynamicSharedMemorySize, SMEM_GEMM);
    cudaFuncSetAttribute(scan2, cudaFuncAttributeMaxDynamicSharedMemorySize, SMEM_SCAN);

    // ---- fork: CSR build on side stream, GEMM chain on main stream ----
    cudaEventRecord(s_fork, 0);
    cudaStreamWaitEvent(s_side, s_fork, 0);

    {   // CSR build (side stream)
        int nbe1 = cdiv(E_nn, T), nbe2 = cdiv(E_in, T);
        zero_deg2<<<cdiv(N_NEWS, T), T, 0, s_side>>>(deg_nn, deg_in, N_NEWS);
        hist2<<<nbe1 + nbe2, T, 0, s_side>>>(edge_nn, E_nn, deg_nn, edge_in, E_in, deg_in, nbe1);
        scan2<<<2, 1024, SMEM_SCAN, s_side>>>(deg_nn, rp_nn, cur_nn, deg_in, rp_in, cur_in, N_NEWS);
        scatter2<<<nbe1 + nbe2, T, 0, s_side>>>(edge_nn, E_nn, cur_nn, csr_nn,
                                                edge_in, E_in, cur_in, csr_in, nbe1);
        cudaEventRecord(s_join, s_side);
    }

    // ---- main stream: weight prep + projections (fp16 mma) + attention dots ----
    transpose_all<<<cdiv(128 * 384, T), T>>>(W_news, W_inter, Wk, BtNh, BtIh, BtK, accsem);
    const int nb1 = cdiv(N_NEWS, 128), nb2 = cdiv(N_INTER, 128);
    mma_gemm_h<<<nb1 + nb2, 256, SMEM_GEMM>>>(x_news, x_inter, BtNh, BtIh, b_news, b_inter,
                                              h_news, h_inter, hh_news, hh_inter,
                                              N_NEWS, N_INTER, nb1, 768);
    {
        int nbA = cdiv(N_NEWS * NH, T), nbB = cdiv(N_INTER * NH, T);
        att_all<<<nbA + nbB, T>>>(h_news, h_inter, a_src_nn, a_dst_nn, a_dst_in, a_src_in,
                                  asrc_nn, adst_nn, adst_in, asrc_in, nbA);
    }

    // ---- join: aggregation needs CSR + h + att ----
    cudaStreamWaitEvent(0, s_join, 0);
    han_agg2<<<cdiv(2 * N_NEWS * 32, T), T>>>(rp_nn, csr_nn, asrc_nn, adst_nn, hh_news, out_nn,
                                              rp_in, csr_in, asrc_in, adst_in, hh_inter, out_in);

    // ---- semantic attention (tf32 mma, merged dual-part) ----
    mma_gemm<<<2 * nb1, 256, SMEM_GEMM>>>(out_nn, out_in, BtK, BtK, bk, bk,
                                          accsem, accsem + 128, N_NEWS, N_NEWS, nb1, 128);
    beta_kernel<<<1, 128>>>(accsem, q, beta);

    // ---- fuse + ELU + output head ----
    final_kernel<<<cdiv(N_NEWS * 32, T), T>>>(out_nn, out_in, beta, W_out, b_out, y);
}

// round 15
// speedup vs baseline: 1.0766x; 1.0766x over previous
#include <cuda_runtime.h>
#include <cuda_fp16.h>
#include <math.h>
#include <stdint.h>

#define N_NEWS  30000
#define N_INTER 60000
#define HID 128
#define NH  8
#define HD  16
#define E_NN_CAP 480000
#define E_IN_CAP 960000

// ---------------- scratch (static device globals; no allocation) ----------------
__device__ float    g_h_news [N_NEWS  * HID];
__device__ float    g_h_inter[N_INTER * HID];
__device__ uint32_t g_hh_news [N_NEWS  * 64];   // half2-packed h (for gather)
__device__ uint32_t g_hh_inter[N_INTER * 64];
__device__ float    g_out_nn [N_NEWS  * HID];
__device__ float    g_out_in [N_NEWS  * HID];
__device__ uint32_t g_BtNh   [HID * 384];       // W_news^T, half2-packed [n][k/2]
__device__ uint32_t g_BtIh   [HID * 384];       // W_inter^T, half2-packed
__device__ float    g_BtK    [HID * HID];       // Wk^T, tf32-rounded bits
__device__ float    g_asrc_nn[N_NEWS  * NH];
__device__ float    g_adst_nn[N_NEWS  * NH];
__device__ float    g_asrc_in[N_INTER * NH];
__device__ float    g_adst_in[N_NEWS  * NH];
__device__ int      g_deg_nn [N_NEWS];
__device__ int      g_deg_in [N_NEWS];
__device__ int      g_rp_nn  [N_NEWS + 1];
__device__ int      g_rp_in  [N_NEWS + 1];
__device__ int      g_cur_nn [N_NEWS];
__device__ int      g_cur_in [N_NEWS];
__device__ int      g_csr_nn [E_NN_CAP];
__device__ int      g_csr_in [E_IN_CAP];
__device__ float    g_accsem[2 * HID];
__device__ float    g_beta  [2];

// ---------------- helpers ----------------
static __device__ __forceinline__ uint32_t smem_u32(const void* p) {
    uint32_t r;
    asm("{ .reg .u64 t; cvta.to.shared.u64 t, %1; cvt.u32.u64 %0, t; }" : "=r"(r) : "l"(p));
    return r;
}
static __device__ __forceinline__ uint32_t f2tf(float x) {
    uint32_t r;
    asm("cvt.rna.tf32.f32 %0, %1;" : "=r"(r) : "f"(x));
    return r;
}
static __device__ __forceinline__ void mma_tf32(float* c, const uint32_t* a, const uint32_t* b) {
    asm volatile(
        "mma.sync.aligned.m16n8k8.row.col.f32.tf32.tf32.f32 "
        "{%0,%1,%2,%3},{%4,%5,%6,%7},{%8,%9},{%0,%1,%2,%3};"
        : "+f"(c[0]), "+f"(c[1]), "+f"(c[2]), "+f"(c[3])
        : "r"(a[0]), "r"(a[1]), "r"(a[2]), "r"(a[3]), "r"(b[0]), "r"(b[1]));
}
static __device__ __forceinline__ void mma_f16(float* c, const uint32_t* a, const uint32_t* b) {
    asm volatile(
        "mma.sync.aligned.m16n8k16.row.col.f32.f16.f16.f32 "
        "{%0,%1,%2,%3},{%4,%5,%6,%7},{%8,%9},{%0,%1,%2,%3};"
        : "+f"(c[0]), "+f"(c[1]), "+f"(c[2]), "+f"(c[3])
        : "r"(a[0]), "r"(a[1]), "r"(a[2]), "r"(a[3]), "r"(b[0]), "r"(b[1]));
}
static __device__ __forceinline__ void cp16(uint32_t dst, const void* src) {
    asm volatile("cp.async.cg.shared.global [%0], [%1], 16;" :: "r"(dst), "l"(src));
}
static __device__ __forceinline__ void ldsm4(uint32_t* r, uint32_t addr) {
    asm volatile("ldmatrix.sync.aligned.m8n8.x4.shared.b16 {%0,%1,%2,%3}, [%4];"
                 : "=r"(r[0]), "=r"(r[1]), "=r"(r[2]), "=r"(r[3]) : "r"(addr));
}
__device__ __forceinline__ float lrelu02(float x) { return x > 0.f ? x : 0.2f * x; }
static __device__ __forceinline__ uint32_t pack_h2(float a, float b) {
    __half2 h = __floats2half2_rn(a, b);
    return *reinterpret_cast<uint32_t*>(&h);
}

// ---------------- setup: zero degree counters ----------------
__global__ void zero_deg2(int* __restrict__ d1, int* __restrict__ d2, int n) {
    int i = blockIdx.x * blockDim.x + threadIdx.x;
    if (i < n) { d1[i] = 0; d2[i] = 0; }
}

// ---------------- weight prep: fp16-pack projection weights, tf32 Wk, zero accsem ----------------
__global__ void transpose_all(const float* __restrict__ Wn, const float* __restrict__ Wi,
                              const float* __restrict__ Wk,
                              uint32_t* __restrict__ BtNh, uint32_t* __restrict__ BtIh,
                              float* __restrict__ BtK, float* __restrict__ accsem)
{
    int i = blockIdx.x * blockDim.x + threadIdx.x;
    if (i < 128 * 384) {                 // (n, k-pair)
        int n = i / 384, kp = i % 384;
        BtNh[i] = pack_h2(Wn[(2 * kp) * 128 + n], Wn[(2 * kp + 1) * 128 + n]);
        BtIh[i] = pack_h2(Wi[(2 * kp) * 128 + n], Wi[(2 * kp + 1) * 128 + n]);
    }
    if (i < 128 * 128) {
        int n = i >> 7, k = i & 127;
        BtK[i] = __uint_as_float(f2tf(Wk[k * 128 + n]));
    }
    if (i < 2 * HID) accsem[i] = 0.f;
}

#define LDT 36              // padded row length (32-bit words); 144B rows
#define BUF_F (128 * LDT)   // words per (A or B) tile

// ---------------- fp16 tensor-core GEMM (projection, dual-part, 2-stage) ----------------
// A fp32 in gmem -> cvt to half2 at register-prefetch -> STS; B pre-packed fp16.
// K-chunk = 64 halfs (128B/row, byte-identical geometry to the tf32 kernel).
// Epilogue: C[m,n] = acc + bias[n] (fp32) and Hh[m][n/2] = half2 pair.
__global__ __launch_bounds__(256, 2)
void mma_gemm_h(const float* __restrict__ A1, const float* __restrict__ A2,
                const uint32_t* __restrict__ Bt1, const uint32_t* __restrict__ Bt2,
                const float* __restrict__ bias1, const float* __restrict__ bias2,
                float* __restrict__ C1, float* __restrict__ C2,
                uint32_t* __restrict__ Hh1, uint32_t* __restrict__ Hh2,
                int M1, int M2, int nb1, int K)
{
    extern __shared__ uint32_t smw[];   // [2][A + B] tiles (words)
    __shared__ float s_bias[128];

    const int tid  = threadIdx.x;
    const int warp = tid >> 5;
    const int lane = tid & 31;
    const int group = lane >> 2, tig = lane & 3;
    const int warpM = warp & 3, warpN = warp >> 2;
    const int mbase = warpM * 32, nbase = warpN * 64;

    const float* A; const uint32_t* Bt; const float* bias; float* C; uint32_t* Hh; int M, m0;
    if ((int)blockIdx.x < nb1) {
        A = A1; Bt = Bt1; bias = bias1; C = C1; Hh = Hh1; M = M1; m0 = blockIdx.x * 128;
    } else {
        A = A2; Bt = Bt2; bias = bias2; C = C2; Hh = Hh2; M = M2; m0 = (blockIdx.x - nb1) * 128;
    }
    const int Kw = K >> 1;              // B row length in words

    if (tid < 128) s_bias[tid] = bias[tid];

    float acc[2][8][4];
#pragma unroll
    for (int i = 0; i < 2; i++)
#pragma unroll
        for (int j = 0; j < 8; j++)
#pragma unroll
            for (int l = 0; l < 4; l++) acc[i][j][l] = 0.f;

    const int nchunk = K >> 6;          // 64 halfs per chunk
    const uint32_t smem_b = smem_u32(smw);

    const int rowL = tid >> 3, qL = tid & 7;   // qL: 32B unit within 128B row
    const int blk = lane >> 3, rr = lane & 7;
    const uint32_t offA = (uint32_t)(((mbase + (blk & 1) * 8 + rr) * LDT + (blk >> 1) * 4) * 4);
    const uint32_t offB = (uint32_t)(((nbase + (blk >> 1) * 8 + rr) * LDT + (blk & 1) * 4) * 4);

    // prefetch+convert A chunk into registers (4 rows x 8 floats -> 4x uint4)
    uint4 pa[4];
    auto prefetchA = [&](int c) {
        const int kb = c * 64;
#pragma unroll
        for (int p = 0; p < 4; p++) {
            int row = rowL + 32 * p;
            int m = m0 + row;
            if (m < M) {
                const float4* src = reinterpret_cast<const float4*>(A + (size_t)m * K + kb + qL * 8);
                float4 va = src[0], vb = src[1];
                pa[p] = make_uint4(pack_h2(va.x, va.y), pack_h2(va.z, va.w),
                                   pack_h2(vb.x, vb.y), pack_h2(vb.z, vb.w));
            } else {
                pa[p] = make_uint4(0u, 0u, 0u, 0u);
            }
        }
    };
    auto issueB = [&](int c) {
        const int kbw = c * 32;         // words
        const uint32_t bo = smem_b + ((uint32_t)(((c & 1) * 2 + 1) * BUF_F) << 2);
#pragma unroll
        for (int p = 0; p < 4; p++) {
            int row = rowL + 32 * p;
            cp16(bo + (uint32_t)((row * LDT + qL * 4) << 2),
                 Bt + (size_t)row * Kw + kbw + qL * 4);
        }
        asm volatile("cp.async.commit_group;");
    };

    prefetchA(0);
    issueB(0);

    for (int c = 0; c < nchunk; c++) {
        // store A(c) (already converted) into buf c&1
        uint32_t* Asm = smw + (c & 1) * 2 * BUF_F;
#pragma unroll
        for (int p = 0; p < 4; p++) {
            int row = rowL + 32 * p;
            *reinterpret_cast<uint4*>(Asm + row * LDT + qL * 4) = pa[p];
        }
        if (c + 1 < nchunk) {
            issueB(c + 1);
            asm volatile("cp.async.wait_group 1;");
        } else {
            asm volatile("cp.async.wait_group 0;");
        }
        __syncthreads();
        if (c + 1 < nchunk) prefetchA(c + 1);

        const uint32_t Asb = smem_b + ((uint32_t)((c & 1) * 2 * BUF_F) << 2);
        const uint32_t Bsb = Asb + (uint32_t)(BUF_F << 2);
#pragma unroll
        for (int ks = 0; ks < 4; ks++) {           // 4 x k16 steps (32B each)
            uint32_t af[2][4], bf[8][2];
            ldsm4(af[0], Asb + offA + (uint32_t)(ks * 32));
            ldsm4(af[1], Asb + offA + (uint32_t)(16 * LDT * 4 + ks * 32));
#pragma unroll
            for (int na2 = 0; na2 < 8; na2 += 2) {
                uint32_t t[4];
                ldsm4(t, Bsb + offB + (uint32_t)(na2 * 8 * LDT * 4 + ks * 32));
                bf[na2][0] = t[0]; bf[na2][1] = t[1];
                bf[na2 + 1][0] = t[2]; bf[na2 + 1][1] = t[3];
            }
#pragma unroll
            for (int ma = 0; ma < 2; ma++)
#pragma unroll
                for (int na = 0; na < 8; na++)
                    mma_f16(acc[ma][na], af[ma], bf[na]);
        }
        __syncthreads();
    }

    // -------- epilogue: bias + fp32 store + half2 pack --------
#pragma unroll
    for (int ma = 0; ma < 2; ma++) {
        int row = m0 + mbase + ma * 16 + group;
#pragma unroll
        for (int na = 0; na < 8; na++) {
            int col = nbase + na * 8 + tig * 2;
            if (row < M) {
                float2 v = { acc[ma][na][0] + s_bias[col],
                             acc[ma][na][1] + s_bias[col + 1] };
                *reinterpret_cast<float2*>(C + (size_t)row * 128 + col) = v;
                Hh[(size_t)row * 64 + (col >> 1)] = pack_h2(v.x, v.y);
            }
            if (row + 8 < M) {
                float2 v = { acc[ma][na][2] + s_bias[col],
                             acc[ma][na][3] + s_bias[col + 1] };
                *reinterpret_cast<float2*>(C + (size_t)(row + 8) * 128 + col) = v;
                Hh[(size_t)(row + 8) * 64 + (col >> 1)] = pack_h2(v.x, v.y);
            }
        }
    }
}

// ---------------- tf32 tensor-core GEMM (semantic only, dual-part, 2-stage) ----------------
__global__ __launch_bounds__(256, 2)
void mma_gemm(const float* __restrict__ A1, const float* __restrict__ A2,
              const float* __restrict__ Bt1, const float* __restrict__ Bt2,
              const float* __restrict__ bias1, const float* __restrict__ bias2,
              float* __restrict__ C1, float* __restrict__ C2,
              int M1, int M2, int nb1, int K)
{
    extern __shared__ float smem[];     // [2][A + B] tiles
    __shared__ float s_bias[128];
    __shared__ float s_col[128];

    const int tid  = threadIdx.x;
    const int warp = tid >> 5;
    const int lane = tid & 31;
    const int group = lane >> 2, tig = lane & 3;
    const int warpM = warp & 3, warpN = warp >> 2;
    const int mbase = warpM * 32, nbase = warpN * 64;

    const float* A; const float* Bt; const float* bias; float* C; int M, m0;
    if ((int)blockIdx.x < nb1) {
        A = A1; Bt = Bt1; bias = bias1; C = C1; M = M1; m0 = blockIdx.x * 128;
    } else {
        A = A2; Bt = Bt2; bias = bias2; C = C2; M = M2; m0 = (blockIdx.x - nb1) * 128;
    }

    if (tid < 128) { s_bias[tid] = bias[tid]; s_col[tid] = 0.f; }

    float acc[2][8][4];
#pragma unroll
    for (int i = 0; i < 2; i++)
#pragma unroll
        for (int j = 0; j < 8; j++)
#pragma unroll
            for (int l = 0; l < 4; l++) acc[i][j][l] = 0.f;

    const int nchunk = K >> 5;
    const uint32_t smem_b = smem_u32(smem);

    const int rowL = tid >> 3, qL = tid & 7;
    const int blk = lane >> 3, rr = lane & 7;
    const uint32_t offA = (uint32_t)(((mbase + (blk & 1) * 8 + rr) * LDT + (blk >> 1) * 4) * 4);
    const uint32_t offB = (uint32_t)(((nbase + (blk >> 1) * 8 + rr) * LDT + (blk & 1) * 4) * 4);

    float4 pA[4];
#pragma unroll
    for (int l = 0; l < 4; l++) {
        int m = m0 + rowL + 32 * l;
        pA[l] = (m < M) ? *reinterpret_cast<const float4*>(A + (size_t)m * K + qL * 4)
                        : make_float4(0.f, 0.f, 0.f, 0.f);
    }
#pragma unroll
    for (int l = 0; l < 4; l++) {
        int row = rowL + 32 * l;
        cp16(smem_b + (uint32_t)((BUF_F + row * LDT + qL * 4) << 2),
             Bt + (size_t)row * K + qL * 4);
    }
    asm volatile("cp.async.commit_group;");

    for (int c = 0; c < nchunk; c++) {
#pragma unroll
        for (int l = 0; l < 4; l++) {
            int row = rowL + 32 * l;
            float4 v = pA[l];
            float4 u = make_float4(__uint_as_float(f2tf(v.x)), __uint_as_float(f2tf(v.y)),
                                   __uint_as_float(f2tf(v.z)), __uint_as_float(f2tf(v.w)));
            *reinterpret_cast<float4*>(smem + (c & 1) * 2 * BUF_F + row * LDT + qL * 4) = u;
        }
        if (c + 1 < nchunk) {
            const int kb = (c + 1) * 32;
            const uint32_t bufo2 = (uint32_t)(((c + 1) & 1) * 2 * BUF_F) << 2;
#pragma unroll
            for (int l = 0; l < 4; l++) {
                int row = rowL + 32 * l;
                cp16(smem_b + bufo2 + (uint32_t)((BUF_F + row * LDT + qL * 4) << 2),
                     Bt + (size_t)row * K + kb + qL * 4);
            }
            asm volatile("cp.async.commit_group;");
            asm volatile("cp.async.wait_group 1;");
        } else {
            asm volatile("cp.async.wait_group 0;");
        }
        __syncthreads();
        if (c + 1 < nchunk) {
            const int kb = (c + 1) * 32;
#pragma unroll
            for (int l = 0; l < 4; l++) {
                int m = m0 + rowL + 32 * l;
                pA[l] = (m < M) ? *reinterpret_cast<const float4*>(A + (size_t)m * K + kb + qL * 4)
                                : make_float4(0.f, 0.f, 0.f, 0.f);
            }
        }
        const uint32_t Asb = smem_b + ((uint32_t)((c & 1) * 2 * BUF_F) << 2);
        const uint32_t Bsb = Asb + (uint32_t)(BUF_F << 2);
#pragma unroll
        for (int ks = 0; ks < 4; ks++) {
            uint32_t af[2][4], bf[8][2];
            ldsm4(af[0], Asb + offA + (uint32_t)((ks * 8) << 2));
            ldsm4(af[1], Asb + offA + (uint32_t)((16 * LDT + ks * 8) << 2));
#pragma unroll
            for (int na2 = 0; na2 < 8; na2 += 2) {
                uint32_t t[4];
                ldsm4(t, Bsb + offB + (uint32_t)((na2 * 8 * LDT + ks * 8) << 2));
                bf[na2][0] = t[0]; bf[na2][1] = t[1];
                bf[na2 + 1][0] = t[2]; bf[na2 + 1][1] = t[3];
            }
#pragma unroll
            for (int ma = 0; ma < 2; ma++)
#pragma unroll
                for (int na = 0; na < 8; na++)
                    mma_tf32(acc[ma][na], af[ma], bf[na]);
        }
        __syncthreads();
    }

    // semantic epilogue: column sums of tanh(acc + bias)
#pragma unroll
    for (int na = 0; na < 8; na++) {
        int col = nbase + na * 8 + tig * 2;
        float p0 = 0.f, p1 = 0.f;
#pragma unroll
        for (int ma = 0; ma < 2; ma++) {
            int row = m0 + mbase + ma * 16 + group;
            if (row < M) {
                p0 += tanhf(acc[ma][na][0] + s_bias[col]);
                p1 += tanhf(acc[ma][na][1] + s_bias[col + 1]);
            }
            if (row + 8 < M) {
                p0 += tanhf(acc[ma][na][2] + s_bias[col]);
                p1 += tanhf(acc[ma][na][3] + s_bias[col + 1]);
            }
        }
        atomicAdd(&s_col[col], p0);
        atomicAdd(&s_col[col + 1], p1);
    }
    __syncthreads();
    if (tid < 128) atomicAdd(&C[tid], s_col[tid]);
}

// ---------------- attention dots, both node types in one launch ----------------
__global__ void att_all(const float* __restrict__ hN, const float* __restrict__ hI,
                        const float* __restrict__ v0, const float* __restrict__ v1,
                        const float* __restrict__ v2, const float* __restrict__ v3,
                        float* __restrict__ o0, float* __restrict__ o1,
                        float* __restrict__ o2, float* __restrict__ o3, int nbA)
{
    __shared__ float sv[4][128];
    if (threadIdx.x < 128) {
        sv[0][threadIdx.x] = v0[threadIdx.x];
        sv[1][threadIdx.x] = v1[threadIdx.x];
        sv[2][threadIdx.x] = v2[threadIdx.x];
        sv[3][threadIdx.x] = v3[threadIdx.x];
    }
    __syncthreads();
    if ((int)blockIdx.x < nbA) {
        int i = blockIdx.x * blockDim.x + threadIdx.x;
        if (i < N_NEWS * NH) {
            int n = i >> 3, hh = i & 7;
            const float* hp = hN + (size_t)n * HID + hh * HD;
            float s0 = 0.f, s1 = 0.f, s2 = 0.f;
#pragma unroll
            for (int d = 0; d < HD; d++) {
                float x = hp[d];
                s0 += x * sv[0][hh * HD + d];
                s1 += x * sv[1][hh * HD + d];
                s2 += x * sv[2][hh * HD + d];
            }
            o0[i] = s0; o1[i] = s1; o2[i] = s2;
        }
    } else {
        int i = (blockIdx.x - nbA) * blockDim.x + threadIdx.x;
        if (i < N_INTER * NH) {
            int n = i >> 3, hh = i & 7;
            const float* hp = hI + (size_t)n * HID + hh * HD;
            float s = 0.f;
#pragma unroll
            for (int d = 0; d < HD; d++) s += hp[d] * sv[3][hh * HD + d];
            o3[i] = s;
        }
    }
}

// ---------------- CSR build (merged dual-edge-type kernels) ----------------
__global__ void hist2(const int* __restrict__ e1, int E1, int* __restrict__ d1,
                      const int* __restrict__ e2, int E2, int* __restrict__ d2, int nb1)
{
    if ((int)blockIdx.x < nb1) {
        int e = blockIdx.x * blockDim.x + threadIdx.x;
        if (e < E1) atomicAdd(&d1[e1[E1 + e]], 1);
    } else {
        int e = (blockIdx.x - nb1) * blockDim.x + threadIdx.x;
        if (e < E2) atomicAdd(&d2[e2[E2 + e]], 1);
    }
}

__global__ __launch_bounds__(1024)
void scan2(const int* __restrict__ degA, int* __restrict__ rpA, int* __restrict__ curA,
           const int* __restrict__ degB, int* __restrict__ rpB, int* __restrict__ curB,
           int n)
{
    extern __shared__ int sdeg[];
    __shared__ int wsum[32];
    const int* deg = blockIdx.x ? degB : degA;
    int* rowptr    = blockIdx.x ? rpB  : rpA;
    int* cursor    = blockIdx.x ? curB : curA;

    const int t = threadIdx.x, lane = t & 31, wid = t >> 5;
    const int chunk = (n + 1023) >> 10;
    const int b = t * chunk;

    for (int i = t; i < n; i += 1024) sdeg[i] = deg[i];
    __syncthreads();

    int v[32];
    int sum = 0;
#pragma unroll
    for (int i = 0; i < 32; i++) {
        if (i < chunk) {
            int idx = b + i;
            int x = (idx < n) ? sdeg[idx] : 0;
            v[i] = sum;
            sum += x;
        }
    }
    int inc = sum;
#pragma unroll
    for (int off = 1; off < 32; off <<= 1) {
        int y = __shfl_up_sync(0xffffffffu, inc, off);
        if (lane >= off) inc += y;
    }
    if (lane == 31) wsum[wid] = inc;
    __syncthreads();
    if (wid == 0) {
        int ws = wsum[lane];
        int winc = ws;
#pragma unroll
        for (int off = 1; off < 32; off <<= 1) {
            int y = __shfl_up_sync(0xffffffffu, winc, off);
            if (lane >= off) winc += y;
        }
        wsum[lane] = winc - ws;
    }
    __syncthreads();
    const int base = wsum[wid] + (inc - sum);
#pragma unroll
    for (int i = 0; i < 32; i++) {
        if (i < chunk) {
            int idx = b + i;
            if (idx < n) sdeg[idx] = base + v[i];
        }
    }
    __syncthreads();
    for (int i = t; i < n; i += 1024) {
        int val = sdeg[i];
        rowptr[i] = val;
        cursor[i] = val;
    }
    if (t == 1023) rowptr[n] = base + sum;
}

__global__ void scatter2(const int* __restrict__ e1, int E1, int* __restrict__ c1, int* __restrict__ s1,
                         const int* __restrict__ e2, int E2, int* __restrict__ c2, int* __restrict__ s2,
                         int nb1)
{
    if ((int)blockIdx.x < nb1) {
        int e = blockIdx.x * blockDim.x + threadIdx.x;
        if (e < E1) { int pos = atomicAdd(&c1[e1[E1 + e]], 1); s1[pos] = e1[e]; }
    } else {
        int e = (blockIdx.x - nb1) * blockDim.x + threadIdx.x;
        if (e < E2) { int pos = atomicAdd(&c2[e2[E2 + e]], 1); s2[pos] = e2[e]; }
    }
}

// ---------------- fused single-pass softmax-aggregation: warp per dst node ----------------
__global__ __launch_bounds__(256)
void han_agg2(const int* __restrict__ rp1, const int* __restrict__ csr1,
              const float* __restrict__ as1, const float* __restrict__ ad1,
              const uint32_t* __restrict__ hh1, float* __restrict__ o1,
              const int* __restrict__ rp2, const int* __restrict__ csr2,
              const float* __restrict__ as2, const float* __restrict__ ad2,
              const uint32_t* __restrict__ hh2, float* __restrict__ o2)
{
    int gtid = blockIdx.x * blockDim.x + threadIdx.x;
    int w = gtid >> 5;
    int lane = threadIdx.x & 31;

    const int* rowptr; const int* csr; const float* asrc; const float* adst;
    const uint32_t* hh; float* out; int d;
    if (w < N_NEWS) {
        d = w; rowptr = rp1; csr = csr1; asrc = as1; adst = ad1; hh = hh1; out = o1;
    } else if (w < 2 * N_NEWS) {
        d = w - N_NEWS; rowptr = rp2; csr = csr2; asrc = as2; adst = ad2; hh = hh2; out = o2;
    } else return;

    const int beg = rowptr[d], end = rowptr[d + 1];
    const int deg = end - beg;
    float4* o = reinterpret_cast<float4*>(out) + (size_t)d * 32 + lane;
    if (deg == 0) { *o = make_float4(0.f, 0.f, 0.f, 0.f); return; }

    const int hdid = lane >> 2;
    const float adh = adst[(size_t)d * 8 + hdid];
    const uint2* h2p = reinterpret_cast<const uint2*>(hh);

    float den = 0.f, a0 = 0.f, a1 = 0.f, a2 = 0.f, a3 = 0.f;
    int i = 0;
    for (; i + 4 <= deg; i += 4) {
        int sA = csr[beg + i],     sB = csr[beg + i + 1];
        int sC = csr[beg + i + 2], sD = csr[beg + i + 3];
        float avA = asrc[(size_t)sA * 8 + hdid];
        float avB = asrc[(size_t)sB * 8 + hdid];
        float avC = asrc[(size_t)sC * 8 + hdid];
        float avD = asrc[(size_t)sD * 8 + hdid];
        uint2 gA = h2p[(size_t)sA * 32 + lane];
        uint2 gB = h2p[(size_t)sB * 32 + lane];
        uint2 gC = h2p[(size_t)sC * 32 + lane];
        uint2 gD = h2p[(size_t)sD * 32 + lane];
        float wA = __expf(lrelu02(avA + adh));
        float wB = __expf(lrelu02(avB + adh));
        float wC = __expf(lrelu02(avC + adh));
        float wD = __expf(lrelu02(avD + adh));
        den += (wA + wB) + (wC + wD);
        float2 lA0 = __half22float2(*reinterpret_cast<__half2*>(&gA.x));
        float2 lA1 = __half22float2(*reinterpret_cast<__half2*>(&gA.y));
        float2 lB0 = __half22float2(*reinterpret_cast<__half2*>(&gB.x));
        float2 lB1 = __half22float2(*reinterpret_cast<__half2*>(&gB.y));
        float2 lC0 = __half22float2(*reinterpret_cast<__half2*>(&gC.x));
        float2 lC1 = __half22float2(*reinterpret_cast<__half2*>(&gC.y));
        float2 lD0 = __half22float2(*reinterpret_cast<__half2*>(&gD.x));
        float2 lD1 = __half22float2(*reinterpret_cast<__half2*>(&gD.y));
        a0 += lA0.x * wA + lB0.x * wB + lC0.x * wC + lD0.x * wD;
        a1 += lA0.y * wA + lB0.y * wB + lC0.y * wC + lD0.y * wD;
        a2 += lA1.x * wA + lB1.x * wB + lC1.x * wC + lD1.x * wD;
        a3 += lA1.y * wA + lB1.y * wB + lC1.y * wC + lD1.y * wD;
    }
    for (; i < deg; i++) {
        int s = csr[beg + i];
        float av = asrc[(size_t)s * 8 + hdid];
        uint2 g = h2p[(size_t)s * 32 + lane];
        float wgt = __expf(lrelu02(av + adh));
        den += wgt;
        float2 l0 = __half22float2(*reinterpret_cast<__half2*>(&g.x));
        float2 l1 = __half22float2(*reinterpret_cast<__half2*>(&g.y));
        a0 += l0.x * wgt; a1 += l0.y * wgt;
        a2 += l1.x * wgt; a3 += l1.y * wgt;
    }
    float invd = 1.f / (den + 1e-16f);
    *o = make_float4(fmaxf(a0 * invd, 0.f), fmaxf(a1 * invd, 0.f),
                     fmaxf(a2 * invd, 0.f), fmaxf(a3 * invd, 0.f));
}

// ---------------- semantic softmax beta ----------------
__global__ void beta_kernel(const float* __restrict__ acc, const float* __restrict__ q,
                            float* __restrict__ beta)
{
    __shared__ float red[2][4];
    int t = threadIdx.x;  // 128 threads
    float s0 = q[t] * acc[t]       * (1.f / N_NEWS);
    float s1 = q[t] * acc[128 + t] * (1.f / N_NEWS);
#pragma unroll
    for (int off = 16; off; off >>= 1) {
        s0 += __shfl_down_sync(0xffffffffu, s0, off);
        s1 += __shfl_down_sync(0xffffffffu, s1, off);
    }
    if ((t & 31) == 0) { red[0][t >> 5] = s0; red[1][t >> 5] = s1; }
    __syncthreads();
    if (t == 0) {
        float sc0 = red[0][0] + red[0][1] + red[0][2] + red[0][3];
        float sc1 = red[1][0] + red[1][1] + red[1][2] + red[1][3];
        float mx = fmaxf(sc0, sc1);
        float e0 = __expf(sc0 - mx), e1 = __expf(sc1 - mx);
        float inv = 1.f / (e0 + e1);
        beta[0] = e0 * inv;
        beta[1] = e1 * inv;
    }
}

// ---------------- final: fuse + ELU + [128x4] head (warp per node) ----------------
__global__ void final_kernel(const float* __restrict__ onn, const float* __restrict__ oin,
                             const float* __restrict__ beta, const float* __restrict__ Wout,
                             const float* __restrict__ bout, float* __restrict__ y)
{
    __shared__ float sw[HID * 4];
    for (int i = threadIdx.x; i < HID * 4; i += blockDim.x) sw[i] = Wout[i];
    __syncthreads();

    int gtid = blockIdx.x * blockDim.x + threadIdx.x;
    int node = gtid >> 5;
    int lane = threadIdx.x & 31;
    if (node >= N_NEWS) return;

    float b0 = beta[0], b1 = beta[1];
    float4 a = reinterpret_cast<const float4*>(onn)[(size_t)node * 32 + lane];
    float4 b = reinterpret_cast<const float4*>(oin)[(size_t)node * 32 + lane];
    float f[4] = { b0 * a.x + b1 * b.x, b0 * a.y + b1 * b.y,
                   b0 * a.z + b1 * b.z, b0 * a.w + b1 * b.w };
#pragma unroll
    for (int u = 0; u < 4; u++) f[u] = f[u] > 0.f ? f[u] : (__expf(f[u]) - 1.f);

    float p[4] = { 0.f, 0.f, 0.f, 0.f };
#pragma unroll
    for (int u = 0; u < 4; u++) {
        int r = lane * 4 + u;
#pragma unroll
        for (int c = 0; c < 4; c++) p[c] += f[u] * sw[r * 4 + c];
    }
#pragma unroll
    for (int off = 16; off; off >>= 1)
#pragma unroll
        for (int c = 0; c < 4; c++) p[c] += __shfl_down_sync(0xffffffffu, p[c], off);
    if (lane == 0) {
#pragma unroll
        for (int c = 0; c < 4; c++) y[(size_t)node * 4 + c] = p[c] + bout[c];
    }
}

// ---------------- host ----------------
static inline int cdiv(int a, int b) { return (a + b - 1) / b; }

extern "C" void kernel_launch(void* const* d_in, const int* in_sizes, int n_in,
                              void* d_out, int out_size)
{
    const float* x_news   = (const float*)d_in[0];
    const float* x_inter  = (const float*)d_in[1];
    const int*   edge_nn  = (const int*)  d_in[2];
    const int*   edge_in  = (const int*)  d_in[3];
    const float* W_news   = (const float*)d_in[4];
    const float* b_news   = (const float*)d_in[5];
    const float* W_inter  = (const float*)d_in[6];
    const float* b_inter  = (const float*)d_in[7];
    const float* a_src_nn = (const float*)d_in[8];
    const float* a_dst_nn = (const float*)d_in[9];
    const float* a_src_in = (const float*)d_in[10];
    const float* a_dst_in = (const float*)d_in[11];
    const float* Wk       = (const float*)d_in[12];
    const float* bk       = (const float*)d_in[13];
    const float* q        = (const float*)d_in[14];
    const float* W_out    = (const float*)d_in[15];
    const float* b_out    = (const float*)d_in[16];
    float* y = (float*)d_out;

    const int E_nn = in_sizes[2] / 2;
    const int E_in = in_sizes[3] / 2;

    float *h_news, *h_inter, *out_nn, *out_in, *BtK;
    float *asrc_nn, *adst_nn, *asrc_in, *adst_in, *accsem, *beta;
    uint32_t *hh_news, *hh_inter, *BtNh, *BtIh;
    int *deg_nn, *deg_in, *rp_nn, *rp_in, *cur_nn, *cur_in, *csr_nn, *csr_in;
    cudaGetSymbolAddress((void**)&h_news,  g_h_news);
    cudaGetSymbolAddress((void**)&h_inter, g_h_inter);
    cudaGetSymbolAddress((void**)&hh_news, g_hh_news);
    cudaGetSymbolAddress((void**)&hh_inter,g_hh_inter);
    cudaGetSymbolAddress((void**)&out_nn,  g_out_nn);
    cudaGetSymbolAddress((void**)&out_in,  g_out_in);
    cudaGetSymbolAddress((void**)&BtNh,    g_BtNh);
    cudaGetSymbolAddress((void**)&BtIh,    g_BtIh);
    cudaGetSymbolAddress((void**)&BtK,     g_BtK);
    cudaGetSymbolAddress((void**)&asrc_nn, g_asrc_nn);
    cudaGetSymbolAddress((void**)&adst_nn, g_adst_nn);
    cudaGetSymbolAddress((void**)&asrc_in, g_asrc_in);
    cudaGetSymbolAddress((void**)&adst_in, g_adst_in);
    cudaGetSymbolAddress((void**)&deg_nn,  g_deg_nn);
    cudaGetSymbolAddress((void**)&deg_in,  g_deg_in);
    cudaGetSymbolAddress((void**)&rp_nn,   g_rp_nn);
    cudaGetSymbolAddress((void**)&rp_in,   g_rp_in);
    cudaGetSymbolAddress((void**)&cur_nn,  g_cur_nn);
    cudaGetSymbolAddress((void**)&cur_in,  g_cur_in);
    cudaGetSymbolAddress((void**)&csr_nn,  g_csr_nn);
    cudaGetSymbolAddress((void**)&csr_in,  g_csr_in);
    cudaGetSymbolAddress((void**)&accsem,  g_accsem);
    cudaGetSymbolAddress((void**)&beta,    g_beta);

    // lazy one-time side stream + fork/join events
    static cudaStream_t s_side = nullptr;
    static cudaEvent_t  s_fork = nullptr, s_join = nullptr;
    if (!s_side) {
        cudaStreamCreateWithFlags(&s_side, cudaStreamNonBlocking);
        cudaEventCreateWithFlags(&s_fork, cudaEventDisableTiming);
        cudaEventCreateWithFlags(&s_join, cudaEventDisableTiming);
    }

    const int T = 256;
    const int SMEM_GEMM = 2 * 2 * BUF_F * 4;   // 73728 bytes (2 CTA/SM)
    const int SMEM_SCAN = N_NEWS * 4;          // 120000 bytes
    cudaFuncSetAttribute(mma_gemm, cudaFuncAttributeMaxDynamicSharedMemorySize, SMEM_GEMM);
    cudaFuncSetAttribute(mma_gemm_h, cudaFuncAttributeMaxDynamicSharedMemorySize, SMEM_GEMM);
    cudaFuncSetAttribute(scan2, cudaFuncAttributeMaxDynamicSharedMemorySize, SMEM_SCAN);

    // ---- fork: CSR build on side stream, GEMM chain on main stream ----
    cudaEventRecord(s_fork, 0);
    cudaStreamWaitEvent(s_side, s_fork, 0);

    {   // CSR build (side stream)
        int nbe1 = cdiv(E_nn, T), nbe2 = cdiv(E_in, T);
        zero_deg2<<<cdiv(N_NEWS, T), T, 0, s_side>>>(deg_nn, deg_in, N_NEWS);
        hist2<<<nbe1 + nbe2, T, 0, s_side>>>(edge_nn, E_nn, deg_nn, edge_in, E_in, deg_in, nbe1);
        scan2<<<2, 1024, SMEM_SCAN, s_side>>>(deg_nn, rp_nn, cur_nn, deg_in, rp_in, cur_in, N_NEWS);
        scatter2<<<nbe1 + nbe2, T, 0, s_side>>>(edge_nn, E_nn, cur_nn, csr_nn,
                                                edge_in, E_in, cur_in, csr_in, nbe1);
        cudaEventRecord(s_join, s_side);
    }

    // ---- main stream: weight prep + projections (fp16 mma) + attention dots ----
    transpose_all<<<cdiv(128 * 384, T), T>>>(W_news, W_inter, Wk, BtNh, BtIh, BtK, accsem);
    const int nb1 = cdiv(N_NEWS, 128), nb2 = cdiv(N_INTER, 128);
    mma_gemm_h<<<nb1 + nb2, 256, SMEM_GEMM>>>(x_news, x_inter, BtNh, BtIh, b_news, b_inter,
                                              h_news, h_inter, hh_news, hh_inter,
                                              N_NEWS, N_INTER, nb1, 768);
    {
        int nbA = cdiv(N_NEWS * NH, T), nbB = cdiv(N_INTER * NH, T);
        att_all<<<nbA + nbB, T>>>(h_news, h_inter, a_src_nn, a_dst_nn, a_dst_in, a_src_in,
                                  asrc_nn, adst_nn, adst_in, asrc_in, nbA);
    }

    // ---- join: aggregation needs CSR + h + att ----
    cudaStreamWaitEvent(0, s_join, 0);
    han_agg2<<<cdiv(2 * N_NEWS * 32, T), T>>>(rp_nn, csr_nn, asrc_nn, adst_nn, hh_news, out_nn,
                                              rp_in, csr_in, asrc_in, adst_in, hh_inter, out_in);

    // ---- semantic attention (tf32 mma, merged dual-part) ----
    mma_gemm<<<2 * nb1, 256, SMEM_GEMM>>>(out_nn, out_in, BtK, BtK, bk, bk,
                                          accsem, accsem + 128, N_NEWS, N_NEWS, nb1, 128);
    beta_kernel<<<1, 128>>>(accsem, q, beta);

    // ---- fuse + ELU + output head ----
    final_kernel<<<cdiv(N_NEWS * 32, T), T>>>(out_nn, out_in, beta, W_out, b_out, y);
}

// round 16
// speedup vs baseline: 1.0900x; 1.0124x over previous
#include <cuda_runtime.h>
#include <cuda_fp16.h>
#include <math.h>
#include <stdint.h>

#define N_NEWS  30000
#define N_INTER 60000
#define HID 128
#define NH  8
#define HD  16
#define E_NN_CAP 480000
#define E_IN_CAP 960000

// ---------------- scratch (static device globals; no allocation) ----------------
__device__ float    g_h_news [N_NEWS  * HID];
__device__ float    g_h_inter[N_INTER * HID];
__device__ uint32_t g_hh_news [N_NEWS  * 64];   // half2-packed h (for gather)
__device__ uint32_t g_hh_inter[N_INTER * 64];
__device__ uint32_t g_oh_nn  [N_NEWS  * 64];    // half2-packed metapath outputs
__device__ uint32_t g_oh_in  [N_NEWS  * 64];
__device__ uint32_t g_BtNh   [HID * 384];       // W_news^T, half2-packed [n][k/2]
__device__ uint32_t g_BtIh   [HID * 384];       // W_inter^T, half2-packed
__device__ uint32_t g_BtKh   [HID * 64];        // Wk^T, half2-packed [n][k/2]
__device__ float    g_asrc_nn[N_NEWS  * NH];
__device__ float    g_adst_nn[N_NEWS  * NH];
__device__ float    g_asrc_in[N_INTER * NH];
__device__ float    g_adst_in[N_NEWS  * NH];
__device__ int      g_deg_nn [N_NEWS];
__device__ int      g_deg_in [N_NEWS];
__device__ int      g_rp_nn  [N_NEWS + 1];
__device__ int      g_rp_in  [N_NEWS + 1];
__device__ int      g_cur_nn [N_NEWS];
__device__ int      g_cur_in [N_NEWS];
__device__ int      g_csr_nn [E_NN_CAP];
__device__ int      g_csr_in [E_IN_CAP];
__device__ float    g_accsem[2 * HID];
__device__ float    g_beta  [2];

// ---------------- helpers ----------------
static __device__ __forceinline__ uint32_t smem_u32(const void* p) {
    uint32_t r;
    asm("{ .reg .u64 t; cvta.to.shared.u64 t, %1; cvt.u32.u64 %0, t; }" : "=r"(r) : "l"(p));
    return r;
}
static __device__ __forceinline__ void mma_f16(float* c, const uint32_t* a, const uint32_t* b) {
    asm volatile(
        "mma.sync.aligned.m16n8k16.row.col.f32.f16.f16.f32 "
        "{%0,%1,%2,%3},{%4,%5,%6,%7},{%8,%9},{%0,%1,%2,%3};"
        : "+f"(c[0]), "+f"(c[1]), "+f"(c[2]), "+f"(c[3])
        : "r"(a[0]), "r"(a[1]), "r"(a[2]), "r"(a[3]), "r"(b[0]), "r"(b[1]));
}
static __device__ __forceinline__ void cp16(uint32_t dst, const void* src) {
    asm volatile("cp.async.cg.shared.global [%0], [%1], 16;" :: "r"(dst), "l"(src));
}
static __device__ __forceinline__ void ldsm4(uint32_t* r, uint32_t addr) {
    asm volatile("ldmatrix.sync.aligned.m8n8.x4.shared.b16 {%0,%1,%2,%3}, [%4];"
                 : "=r"(r[0]), "=r"(r[1]), "=r"(r[2]), "=r"(r[3]) : "r"(addr));
}
__device__ __forceinline__ float lrelu02(float x) { return x > 0.f ? x : 0.2f * x; }
static __device__ __forceinline__ uint32_t pack_h2(float a, float b) {
    __half2 h = __floats2half2_rn(a, b);
    return *reinterpret_cast<uint32_t*>(&h);
}

// ---------------- setup: zero degree counters ----------------
__global__ void zero_deg2(int* __restrict__ d1, int* __restrict__ d2, int n) {
    int i = blockIdx.x * blockDim.x + threadIdx.x;
    if (i < n) { d1[i] = 0; d2[i] = 0; }
}

// ---------------- weight prep: fp16-pack all weights, zero accsem ----------------
__global__ void transpose_all(const float* __restrict__ Wn, const float* __restrict__ Wi,
                              const float* __restrict__ Wk,
                              uint32_t* __restrict__ BtNh, uint32_t* __restrict__ BtIh,
                              uint32_t* __restrict__ BtKh, float* __restrict__ accsem)
{
    int i = blockIdx.x * blockDim.x + threadIdx.x;
    if (i < 128 * 384) {                 // (n, k-pair)
        int n = i / 384, kp = i % 384;
        BtNh[i] = pack_h2(Wn[(2 * kp) * 128 + n], Wn[(2 * kp + 1) * 128 + n]);
        BtIh[i] = pack_h2(Wi[(2 * kp) * 128 + n], Wi[(2 * kp + 1) * 128 + n]);
    }
    if (i < 128 * 64) {
        int n = i >> 6, kp = i & 63;
        BtKh[i] = pack_h2(Wk[(2 * kp) * 128 + n], Wk[(2 * kp + 1) * 128 + n]);
    }
    if (i < 2 * HID) accsem[i] = 0.f;
}

#define LDT 36              // padded row length (32-bit words); 144B rows
#define BUF_F (128 * LDT)   // words per (A or B) tile

// ---------------- fp16 tensor-core GEMM (projection, dual-part, 2-stage) ----------------
// A fp32 in gmem -> cvt to half2 at register-prefetch -> STS; B pre-packed fp16.
// Epilogue: C[m,n] = acc + bias[n] (fp32) and Hh[m][n/2] = half2 pair.
__global__ __launch_bounds__(256, 2)
void mma_gemm_h(const float* __restrict__ A1, const float* __restrict__ A2,
                const uint32_t* __restrict__ Bt1, const uint32_t* __restrict__ Bt2,
                const float* __restrict__ bias1, const float* __restrict__ bias2,
                float* __restrict__ C1, float* __restrict__ C2,
                uint32_t* __restrict__ Hh1, uint32_t* __restrict__ Hh2,
                int M1, int M2, int nb1, int K)
{
    extern __shared__ uint32_t smw[];   // [2][A + B] tiles (words)
    __shared__ float s_bias[128];

    const int tid  = threadIdx.x;
    const int warp = tid >> 5;
    const int lane = tid & 31;
    const int group = lane >> 2, tig = lane & 3;
    const int warpM = warp & 3, warpN = warp >> 2;
    const int mbase = warpM * 32, nbase = warpN * 64;

    const float* A; const uint32_t* Bt; const float* bias; float* C; uint32_t* Hh; int M, m0;
    if ((int)blockIdx.x < nb1) {
        A = A1; Bt = Bt1; bias = bias1; C = C1; Hh = Hh1; M = M1; m0 = blockIdx.x * 128;
    } else {
        A = A2; Bt = Bt2; bias = bias2; C = C2; Hh = Hh2; M = M2; m0 = (blockIdx.x - nb1) * 128;
    }
    const int Kw = K >> 1;              // B row length in words

    if (tid < 128) s_bias[tid] = bias[tid];

    float acc[2][8][4];
#pragma unroll
    for (int i = 0; i < 2; i++)
#pragma unroll
        for (int j = 0; j < 8; j++)
#pragma unroll
            for (int l = 0; l < 4; l++) acc[i][j][l] = 0.f;

    const int nchunk = K >> 6;          // 64 halfs per chunk
    const uint32_t smem_b = smem_u32(smw);

    const int rowL = tid >> 3, qL = tid & 7;   // qL: 32B unit within 128B row
    const int blk = lane >> 3, rr = lane & 7;
    const uint32_t offA = (uint32_t)(((mbase + (blk & 1) * 8 + rr) * LDT + (blk >> 1) * 4) * 4);
    const uint32_t offB = (uint32_t)(((nbase + (blk >> 1) * 8 + rr) * LDT + (blk & 1) * 4) * 4);

    uint4 pa[4];
    auto prefetchA = [&](int c) {
        const int kb = c * 64;
#pragma unroll
        for (int p = 0; p < 4; p++) {
            int row = rowL + 32 * p;
            int m = m0 + row;
            if (m < M) {
                const float4* src = reinterpret_cast<const float4*>(A + (size_t)m * K + kb + qL * 8);
                float4 va = src[0], vb = src[1];
                pa[p] = make_uint4(pack_h2(va.x, va.y), pack_h2(va.z, va.w),
                                   pack_h2(vb.x, vb.y), pack_h2(vb.z, vb.w));
            } else {
                pa[p] = make_uint4(0u, 0u, 0u, 0u);
            }
        }
    };
    auto issueB = [&](int c) {
        const int kbw = c * 32;
        const uint32_t bo = smem_b + ((uint32_t)(((c & 1) * 2 + 1) * BUF_F) << 2);
#pragma unroll
        for (int p = 0; p < 4; p++) {
            int row = rowL + 32 * p;
            cp16(bo + (uint32_t)((row * LDT + qL * 4) << 2),
                 Bt + (size_t)row * Kw + kbw + qL * 4);
        }
        asm volatile("cp.async.commit_group;");
    };

    prefetchA(0);
    issueB(0);

    for (int c = 0; c < nchunk; c++) {
        uint32_t* Asm = smw + (c & 1) * 2 * BUF_F;
#pragma unroll
        for (int p = 0; p < 4; p++) {
            int row = rowL + 32 * p;
            *reinterpret_cast<uint4*>(Asm + row * LDT + qL * 4) = pa[p];
        }
        if (c + 1 < nchunk) {
            issueB(c + 1);
            asm volatile("cp.async.wait_group 1;");
        } else {
            asm volatile("cp.async.wait_group 0;");
        }
        __syncthreads();
        if (c + 1 < nchunk) prefetchA(c + 1);

        const uint32_t Asb = smem_b + ((uint32_t)((c & 1) * 2 * BUF_F) << 2);
        const uint32_t Bsb = Asb + (uint32_t)(BUF_F << 2);
#pragma unroll
        for (int ks = 0; ks < 4; ks++) {
            uint32_t af[2][4], bf[8][2];
            ldsm4(af[0], Asb + offA + (uint32_t)(ks * 32));
            ldsm4(af[1], Asb + offA + (uint32_t)(16 * LDT * 4 + ks * 32));
#pragma unroll
            for (int na2 = 0; na2 < 8; na2 += 2) {
                uint32_t t[4];
                ldsm4(t, Bsb + offB + (uint32_t)(na2 * 8 * LDT * 4 + ks * 32));
                bf[na2][0] = t[0]; bf[na2][1] = t[1];
                bf[na2 + 1][0] = t[2]; bf[na2 + 1][1] = t[3];
            }
#pragma unroll
            for (int ma = 0; ma < 2; ma++)
#pragma unroll
                for (int na = 0; na < 8; na++)
                    mma_f16(acc[ma][na], af[ma], bf[na]);
        }
        __syncthreads();
    }

    // epilogue: bias + fp32 store + half2 pack
#pragma unroll
    for (int ma = 0; ma < 2; ma++) {
        int row = m0 + mbase + ma * 16 + group;
#pragma unroll
        for (int na = 0; na < 8; na++) {
            int col = nbase + na * 8 + tig * 2;
            if (row < M) {
                float2 v = { acc[ma][na][0] + s_bias[col],
                             acc[ma][na][1] + s_bias[col + 1] };
                *reinterpret_cast<float2*>(C + (size_t)row * 128 + col) = v;
                Hh[(size_t)row * 64 + (col >> 1)] = pack_h2(v.x, v.y);
            }
            if (row + 8 < M) {
                float2 v = { acc[ma][na][2] + s_bias[col],
                             acc[ma][na][3] + s_bias[col + 1] };
                *reinterpret_cast<float2*>(C + (size_t)(row + 8) * 128 + col) = v;
                Hh[(size_t)(row + 8) * 64 + (col >> 1)] = pack_h2(v.x, v.y);
            }
        }
    }
}

// ---------------- fp16 tensor-core GEMM (semantic, dual-part, A pre-packed) ----------------
// A: half2-packed [M][64 words], B: half2-packed Wk^T. Both via cp.async (no cvt).
// Epilogue: atomicAdd(C[n], sum_{m<M} tanh(acc + bias[n]))
__global__ __launch_bounds__(256, 2)
void mma_gemm_hs(const uint32_t* __restrict__ A1, const uint32_t* __restrict__ A2,
                 const uint32_t* __restrict__ Bt,
                 const float* __restrict__ bias,
                 float* __restrict__ C1, float* __restrict__ C2,
                 int M1, int M2, int nb1, int K)
{
    extern __shared__ uint32_t smw[];
    __shared__ float s_bias[128];
    __shared__ float s_col[128];

    const int tid  = threadIdx.x;
    const int warp = tid >> 5;
    const int lane = tid & 31;
    const int group = lane >> 2, tig = lane & 3;
    const int warpM = warp & 3, warpN = warp >> 2;
    const int mbase = warpM * 32, nbase = warpN * 64;

    const uint32_t* A; float* C; int M, m0;
    if ((int)blockIdx.x < nb1) { A = A1; C = C1; M = M1; m0 = blockIdx.x * 128; }
    else                       { A = A2; C = C2; M = M2; m0 = (blockIdx.x - nb1) * 128; }
    const int Kw = K >> 1;              // row length in words (64)

    if (tid < 128) { s_bias[tid] = bias[tid]; s_col[tid] = 0.f; }

    float acc[2][8][4];
#pragma unroll
    for (int i = 0; i < 2; i++)
#pragma unroll
        for (int j = 0; j < 8; j++)
#pragma unroll
            for (int l = 0; l < 4; l++) acc[i][j][l] = 0.f;

    const int nchunk = K >> 6;          // 2 for K=128
    const uint32_t smem_b = smem_u32(smw);

    const int rowL = tid >> 3, qL = tid & 7;
    const int blk = lane >> 3, rr = lane & 7;
    const uint32_t offA = (uint32_t)(((mbase + (blk & 1) * 8 + rr) * LDT + (blk >> 1) * 4) * 4);
    const uint32_t offB = (uint32_t)(((nbase + (blk >> 1) * 8 + rr) * LDT + (blk & 1) * 4) * 4);

    auto issue_chunk = [&](int c) {
        const int kbw = c * 32;
        const uint32_t bo = smem_b + ((uint32_t)((c & 1) * 2 * BUF_F) << 2);
#pragma unroll
        for (int p = 0; p < 4; p++) {
            int row = rowL + 32 * p;
            int m = m0 + row;
            // A rows beyond M: clamp to row 0 (masked in epilogue)
            cp16(bo + (uint32_t)((row * LDT + qL * 4) << 2),
                 A + (size_t)(m < M ? m : 0) * Kw + kbw + qL * 4);
            cp16(bo + (uint32_t)((BUF_F + row * LDT + qL * 4) << 2),
                 Bt + (size_t)row * Kw + kbw + qL * 4);
        }
        asm volatile("cp.async.commit_group;");
    };

    issue_chunk(0);
    for (int c = 0; c < nchunk; c++) {
        if (c + 1 < nchunk) {
            issue_chunk(c + 1);
            asm volatile("cp.async.wait_group 1;");
        } else {
            asm volatile("cp.async.wait_group 0;");
        }
        __syncthreads();

        const uint32_t Asb = smem_b + ((uint32_t)((c & 1) * 2 * BUF_F) << 2);
        const uint32_t Bsb = Asb + (uint32_t)(BUF_F << 2);
#pragma unroll
        for (int ks = 0; ks < 4; ks++) {
            uint32_t af[2][4], bf[8][2];
            ldsm4(af[0], Asb + offA + (uint32_t)(ks * 32));
            ldsm4(af[1], Asb + offA + (uint32_t)(16 * LDT * 4 + ks * 32));
#pragma unroll
            for (int na2 = 0; na2 < 8; na2 += 2) {
                uint32_t t[4];
                ldsm4(t, Bsb + offB + (uint32_t)(na2 * 8 * LDT * 4 + ks * 32));
                bf[na2][0] = t[0]; bf[na2][1] = t[1];
                bf[na2 + 1][0] = t[2]; bf[na2 + 1][1] = t[3];
            }
#pragma unroll
            for (int ma = 0; ma < 2; ma++)
#pragma unroll
                for (int na = 0; na < 8; na++)
                    mma_f16(acc[ma][na], af[ma], bf[na]);
        }
        __syncthreads();
    }

    // semantic epilogue: column sums of tanh(acc + bias)
#pragma unroll
    for (int na = 0; na < 8; na++) {
        int col = nbase + na * 8 + tig * 2;
        float p0 = 0.f, p1 = 0.f;
#pragma unroll
        for (int ma = 0; ma < 2; ma++) {
            int row = m0 + mbase + ma * 16 + group;
            if (row < M) {
                p0 += tanhf(acc[ma][na][0] + s_bias[col]);
                p1 += tanhf(acc[ma][na][1] + s_bias[col + 1]);
            }
            if (row + 8 < M) {
                p0 += tanhf(acc[ma][na][2] + s_bias[col]);
                p1 += tanhf(acc[ma][na][3] + s_bias[col + 1]);
            }
        }
        atomicAdd(&s_col[col], p0);
        atomicAdd(&s_col[col + 1], p1);
    }
    __syncthreads();
    if (tid < 128) atomicAdd(&C[tid], s_col[tid]);
}

// ---------------- attention dots, both node types in one launch ----------------
__global__ void att_all(const float* __restrict__ hN, const float* __restrict__ hI,
                        const float* __restrict__ v0, const float* __restrict__ v1,
                        const float* __restrict__ v2, const float* __restrict__ v3,
                        float* __restrict__ o0, float* __restrict__ o1,
                        float* __restrict__ o2, float* __restrict__ o3, int nbA)
{
    __shared__ float sv[4][128];
    if (threadIdx.x < 128) {
        sv[0][threadIdx.x] = v0[threadIdx.x];
        sv[1][threadIdx.x] = v1[threadIdx.x];
        sv[2][threadIdx.x] = v2[threadIdx.x];
        sv[3][threadIdx.x] = v3[threadIdx.x];
    }
    __syncthreads();
    if ((int)blockIdx.x < nbA) {
        int i = blockIdx.x * blockDim.x + threadIdx.x;
        if (i < N_NEWS * NH) {
            int n = i >> 3, hh = i & 7;
            const float* hp = hN + (size_t)n * HID + hh * HD;
            float s0 = 0.f, s1 = 0.f, s2 = 0.f;
#pragma unroll
            for (int d = 0; d < HD; d++) {
                float x = hp[d];
                s0 += x * sv[0][hh * HD + d];
                s1 += x * sv[1][hh * HD + d];
                s2 += x * sv[2][hh * HD + d];
            }
            o0[i] = s0; o1[i] = s1; o2[i] = s2;
        }
    } else {
        int i = (blockIdx.x - nbA) * blockDim.x + threadIdx.x;
        if (i < N_INTER * NH) {
            int n = i >> 3, hh = i & 7;
            const float* hp = hI + (size_t)n * HID + hh * HD;
            float s = 0.f;
#pragma unroll
            for (int d = 0; d < HD; d++) s += hp[d] * sv[3][hh * HD + d];
            o3[i] = s;
        }
    }
}

// ---------------- CSR build (merged dual-edge-type kernels) ----------------
__global__ void hist2(const int* __restrict__ e1, int E1, int* __restrict__ d1,
                      const int* __restrict__ e2, int E2, int* __restrict__ d2, int nb1)
{
    if ((int)blockIdx.x < nb1) {
        int e = blockIdx.x * blockDim.x + threadIdx.x;
        if (e < E1) atomicAdd(&d1[e1[E1 + e]], 1);
    } else {
        int e = (blockIdx.x - nb1) * blockDim.x + threadIdx.x;
        if (e < E2) atomicAdd(&d2[e2[E2 + e]], 1);
    }
}

__global__ __launch_bounds__(1024)
void scan2(const int* __restrict__ degA, int* __restrict__ rpA, int* __restrict__ curA,
           const int* __restrict__ degB, int* __restrict__ rpB, int* __restrict__ curB,
           int n)
{
    extern __shared__ int sdeg[];
    __shared__ int wsum[32];
    const int* deg = blockIdx.x ? degB : degA;
    int* rowptr    = blockIdx.x ? rpB  : rpA;
    int* cursor    = blockIdx.x ? curB : curA;

    const int t = threadIdx.x, lane = t & 31, wid = t >> 5;
    const int chunk = (n + 1023) >> 10;
    const int b = t * chunk;

    for (int i = t; i < n; i += 1024) sdeg[i] = deg[i];
    __syncthreads();

    int v[32];
    int sum = 0;
#pragma unroll
    for (int i = 0; i < 32; i++) {
        if (i < chunk) {
            int idx = b + i;
            int x = (idx < n) ? sdeg[idx] : 0;
            v[i] = sum;
            sum += x;
        }
    }
    int inc = sum;
#pragma unroll
    for (int off = 1; off < 32; off <<= 1) {
        int y = __shfl_up_sync(0xffffffffu, inc, off);
        if (lane >= off) inc += y;
    }
    if (lane == 31) wsum[wid] = inc;
    __syncthreads();
    if (wid == 0) {
        int ws = wsum[lane];
        int winc = ws;
#pragma unroll
        for (int off = 1; off < 32; off <<= 1) {
            int y = __shfl_up_sync(0xffffffffu, winc, off);
            if (lane >= off) winc += y;
        }
        wsum[lane] = winc - ws;
    }
    __syncthreads();
    const int base = wsum[wid] + (inc - sum);
#pragma unroll
    for (int i = 0; i < 32; i++) {
        if (i < chunk) {
            int idx = b + i;
            if (idx < n) sdeg[idx] = base + v[i];
        }
    }
    __syncthreads();
    for (int i = t; i < n; i += 1024) {
        int val = sdeg[i];
        rowptr[i] = val;
        cursor[i] = val;
    }
    if (t == 1023) rowptr[n] = base + sum;
}

__global__ void scatter2(const int* __restrict__ e1, int E1, int* __restrict__ c1, int* __restrict__ s1,
                         const int* __restrict__ e2, int E2, int* __restrict__ c2, int* __restrict__ s2,
                         int nb1)
{
    if ((int)blockIdx.x < nb1) {
        int e = blockIdx.x * blockDim.x + threadIdx.x;
        if (e < E1) { int pos = atomicAdd(&c1[e1[E1 + e]], 1); s1[pos] = e1[e]; }
    } else {
        int e = (blockIdx.x - nb1) * blockDim.x + threadIdx.x;
        if (e < E2) { int pos = atomicAdd(&c2[e2[E2 + e]], 1); s2[pos] = e2[e]; }
    }
}

// ---------------- fused single-pass softmax-aggregation: warp per dst node ----------------
// fp16 h gather; fp32 accumulate; half2-packed output.
__global__ __launch_bounds__(256)
void han_agg2(const int* __restrict__ rp1, const int* __restrict__ csr1,
              const float* __restrict__ as1, const float* __restrict__ ad1,
              const uint32_t* __restrict__ hh1, uint32_t* __restrict__ o1,
              const int* __restrict__ rp2, const int* __restrict__ csr2,
              const float* __restrict__ as2, const float* __restrict__ ad2,
              const uint32_t* __restrict__ hh2, uint32_t* __restrict__ o2)
{
    int gtid = blockIdx.x * blockDim.x + threadIdx.x;
    int w = gtid >> 5;
    int lane = threadIdx.x & 31;

    const int* rowptr; const int* csr; const float* asrc; const float* adst;
    const uint32_t* hh; uint32_t* out; int d;
    if (w < N_NEWS) {
        d = w; rowptr = rp1; csr = csr1; asrc = as1; adst = ad1; hh = hh1; out = o1;
    } else if (w < 2 * N_NEWS) {
        d = w - N_NEWS; rowptr = rp2; csr = csr2; asrc = as2; adst = ad2; hh = hh2; out = o2;
    } else return;

    const int beg = rowptr[d], end = rowptr[d + 1];
    const int deg = end - beg;
    uint2* o = reinterpret_cast<uint2*>(out) + (size_t)d * 32 + lane;
    if (deg == 0) { *o = make_uint2(0u, 0u); return; }

    const int hdid = lane >> 2;
    const float adh = adst[(size_t)d * 8 + hdid];
    const uint2* h2p = reinterpret_cast<const uint2*>(hh);

    float den = 0.f, a0 = 0.f, a1 = 0.f, a2 = 0.f, a3 = 0.f;
    int i = 0;
    for (; i + 4 <= deg; i += 4) {
        int sA = csr[beg + i],     sB = csr[beg + i + 1];
        int sC = csr[beg + i + 2], sD = csr[beg + i + 3];
        float avA = asrc[(size_t)sA * 8 + hdid];
        float avB = asrc[(size_t)sB * 8 + hdid];
        float avC = asrc[(size_t)sC * 8 + hdid];
        float avD = asrc[(size_t)sD * 8 + hdid];
        uint2 gA = h2p[(size_t)sA * 32 + lane];
        uint2 gB = h2p[(size_t)sB * 32 + lane];
        uint2 gC = h2p[(size_t)sC * 32 + lane];
        uint2 gD = h2p[(size_t)sD * 32 + lane];
        float wA = __expf(lrelu02(avA + adh));
        float wB = __expf(lrelu02(avB + adh));
        float wC = __expf(lrelu02(avC + adh));
        float wD = __expf(lrelu02(avD + adh));
        den += (wA + wB) + (wC + wD);
        float2 lA0 = __half22float2(*reinterpret_cast<__half2*>(&gA.x));
        float2 lA1 = __half22float2(*reinterpret_cast<__half2*>(&gA.y));
        float2 lB0 = __half22float2(*reinterpret_cast<__half2*>(&gB.x));
        float2 lB1 = __half22float2(*reinterpret_cast<__half2*>(&gB.y));
        float2 lC0 = __half22float2(*reinterpret_cast<__half2*>(&gC.x));
        float2 lC1 = __half22float2(*reinterpret_cast<__half2*>(&gC.y));
        float2 lD0 = __half22float2(*reinterpret_cast<__half2*>(&gD.x));
        float2 lD1 = __half22float2(*reinterpret_cast<__half2*>(&gD.y));
        a0 += lA0.x * wA + lB0.x * wB + lC0.x * wC + lD0.x * wD;
        a1 += lA0.y * wA + lB0.y * wB + lC0.y * wC + lD0.y * wD;
        a2 += lA1.x * wA + lB1.x * wB + lC1.x * wC + lD1.x * wD;
        a3 += lA1.y * wA + lB1.y * wB + lC1.y * wC + lD1.y * wD;
    }
    for (; i < deg; i++) {
        int s = csr[beg + i];
        float av = asrc[(size_t)s * 8 + hdid];
        uint2 g = h2p[(size_t)s * 32 + lane];
        float wgt = __expf(lrelu02(av + adh));
        den += wgt;
        float2 l0 = __half22float2(*reinterpret_cast<__half2*>(&g.x));
        float2 l1 = __half22float2(*reinterpret_cast<__half2*>(&g.y));
        a0 += l0.x * wgt; a1 += l0.y * wgt;
        a2 += l1.x * wgt; a3 += l1.y * wgt;
    }
    float invd = 1.f / (den + 1e-16f);
    *o = make_uint2(pack_h2(fmaxf(a0 * invd, 0.f), fmaxf(a1 * invd, 0.f)),
                    pack_h2(fmaxf(a2 * invd, 0.f), fmaxf(a3 * invd, 0.f)));
}

// ---------------- semantic softmax beta ----------------
__global__ void beta_kernel(const float* __restrict__ acc, const float* __restrict__ q,
                            float* __restrict__ beta)
{
    __shared__ float red[2][4];
    int t = threadIdx.x;  // 128 threads
    float s0 = q[t] * acc[t]       * (1.f / N_NEWS);
    float s1 = q[t] * acc[128 + t] * (1.f / N_NEWS);
#pragma unroll
    for (int off = 16; off; off >>= 1) {
        s0 += __shfl_down_sync(0xffffffffu, s0, off);
        s1 += __shfl_down_sync(0xffffffffu, s1, off);
    }
    if ((t & 31) == 0) { red[0][t >> 5] = s0; red[1][t >> 5] = s1; }
    __syncthreads();
    if (t == 0) {
        float sc0 = red[0][0] + red[0][1] + red[0][2] + red[0][3];
        float sc1 = red[1][0] + red[1][1] + red[1][2] + red[1][3];
        float mx = fmaxf(sc0, sc1);
        float e0 = __expf(sc0 - mx), e1 = __expf(sc1 - mx);
        float inv = 1.f / (e0 + e1);
        beta[0] = e0 * inv;
        beta[1] = e1 * inv;
    }
}

// ---------------- final: fuse + ELU + [128x4] head (warp per node, fp16 inputs) ----------------
__global__ void final_kernel(const uint32_t* __restrict__ onn, const uint32_t* __restrict__ oin,
                             const float* __restrict__ beta, const float* __restrict__ Wout,
                             const float* __restrict__ bout, float* __restrict__ y)
{
    __shared__ float sw[HID * 4];
    for (int i = threadIdx.x; i < HID * 4; i += blockDim.x) sw[i] = Wout[i];
    __syncthreads();

    int gtid = blockIdx.x * blockDim.x + threadIdx.x;
    int node = gtid >> 5;
    int lane = threadIdx.x & 31;
    if (node >= N_NEWS) return;

    float b0 = beta[0], b1 = beta[1];
    uint2 ga = reinterpret_cast<const uint2*>(onn)[(size_t)node * 32 + lane];
    uint2 gb = reinterpret_cast<const uint2*>(oin)[(size_t)node * 32 + lane];
    float2 a0 = __half22float2(*reinterpret_cast<__half2*>(&ga.x));
    float2 a1 = __half22float2(*reinterpret_cast<__half2*>(&ga.y));
    float2 c0 = __half22float2(*reinterpret_cast<__half2*>(&gb.x));
    float2 c1 = __half22float2(*reinterpret_cast<__half2*>(&gb.y));
    float f[4] = { b0 * a0.x + b1 * c0.x, b0 * a0.y + b1 * c0.y,
                   b0 * a1.x + b1 * c1.x, b0 * a1.y + b1 * c1.y };   // inputs already relu'd
#pragma unroll
    for (int u = 0; u < 4; u++) f[u] = f[u] > 0.f ? f[u] : (__expf(f[u]) - 1.f);

    float p[4] = { 0.f, 0.f, 0.f, 0.f };
#pragma unroll
    for (int u = 0; u < 4; u++) {
        int r = lane * 4 + u;
#pragma unroll
        for (int c = 0; c < 4; c++) p[c] += f[u] * sw[r * 4 + c];
    }
#pragma unroll
    for (int off = 16; off; off >>= 1)
#pragma unroll
        for (int c = 0; c < 4; c++) p[c] += __shfl_down_sync(0xffffffffu, p[c], off);
    if (lane == 0) {
#pragma unroll
        for (int c = 0; c < 4; c++) y[(size_t)node * 4 + c] = p[c] + bout[c];
    }
}

// ---------------- host ----------------
static inline int cdiv(int a, int b) { return (a + b - 1) / b; }

extern "C" void kernel_launch(void* const* d_in, const int* in_sizes, int n_in,
                              void* d_out, int out_size)
{
    const float* x_news   = (const float*)d_in[0];
    const float* x_inter  = (const float*)d_in[1];
    const int*   edge_nn  = (const int*)  d_in[2];
    const int*   edge_in  = (const int*)  d_in[3];
    const float* W_news   = (const float*)d_in[4];
    const float* b_news   = (const float*)d_in[5];
    const float* W_inter  = (const float*)d_in[6];
    const float* b_inter  = (const float*)d_in[7];
    const float* a_src_nn = (const float*)d_in[8];
    const float* a_dst_nn = (const float*)d_in[9];
    const float* a_src_in = (const float*)d_in[10];
    const float* a_dst_in = (const float*)d_in[11];
    const float* Wk       = (const float*)d_in[12];
    const float* bk       = (const float*)d_in[13];
    const float* q        = (const float*)d_in[14];
    const float* W_out    = (const float*)d_in[15];
    const float* b_out    = (const float*)d_in[16];
    float* y = (float*)d_out;

    const int E_nn = in_sizes[2] / 2;
    const int E_in = in_sizes[3] / 2;

    float *h_news, *h_inter, *asrc_nn, *adst_nn, *asrc_in, *adst_in, *accsem, *beta;
    uint32_t *hh_news, *hh_inter, *oh_nn, *oh_in, *BtNh, *BtIh, *BtKh;
    int *deg_nn, *deg_in, *rp_nn, *rp_in, *cur_nn, *cur_in, *csr_nn, *csr_in;
    cudaGetSymbolAddress((void**)&h_news,  g_h_news);
    cudaGetSymbolAddress((void**)&h_inter, g_h_inter);
    cudaGetSymbolAddress((void**)&hh_news, g_hh_news);
    cudaGetSymbolAddress((void**)&hh_inter,g_hh_inter);
    cudaGetSymbolAddress((void**)&oh_nn,   g_oh_nn);
    cudaGetSymbolAddress((void**)&oh_in,   g_oh_in);
    cudaGetSymbolAddress((void**)&BtNh,    g_BtNh);
    cudaGetSymbolAddress((void**)&BtIh,    g_BtIh);
    cudaGetSymbolAddress((void**)&BtKh,    g_BtKh);
    cudaGetSymbolAddress((void**)&asrc_nn, g_asrc_nn);
    cudaGetSymbolAddress((void**)&adst_nn, g_adst_nn);
    cudaGetSymbolAddress((void**)&asrc_in, g_asrc_in);
    cudaGetSymbolAddress((void**)&adst_in, g_adst_in);
    cudaGetSymbolAddress((void**)&deg_nn,  g_deg_nn);
    cudaGetSymbolAddress((void**)&deg_in,  g_deg_in);
    cudaGetSymbolAddress((void**)&rp_nn,   g_rp_nn);
    cudaGetSymbolAddress((void**)&rp_in,   g_rp_in);
    cudaGetSymbolAddress((void**)&cur_nn,  g_cur_nn);
    cudaGetSymbolAddress((void**)&cur_in,  g_cur_in);
    cudaGetSymbolAddress((void**)&csr_nn,  g_csr_nn);
    cudaGetSymbolAddress((void**)&csr_in,  g_csr_in);
    cudaGetSymbolAddress((void**)&accsem,  g_accsem);
    cudaGetSymbolAddress((void**)&beta,    g_beta);

    // lazy one-time side stream + fork/join events
    static cudaStream_t s_side = nullptr;
    static cudaEvent_t  s_fork = nullptr, s_join = nullptr;
    if (!s_side) {
        cudaStreamCreateWithFlags(&s_side, cudaStreamNonBlocking);
        cudaEventCreateWithFlags(&s_fork, cudaEventDisableTiming);
        cudaEventCreateWithFlags(&s_join, cudaEventDisableTiming);
    }

    const int T = 256;
    const int SMEM_GEMM = 2 * 2 * BUF_F * 4;   // 73728 bytes (2 CTA/SM)
    const int SMEM_SCAN = N_NEWS * 4;          // 120000 bytes
    cudaFuncSetAttribute(mma_gemm_h,  cudaFuncAttributeMaxDynamicSharedMemorySize, SMEM_GEMM);
    cudaFuncSetAttribute(mma_gemm_hs, cudaFuncAttributeMaxDynamicSharedMemorySize, SMEM_GEMM);
    cudaFuncSetAttribute(scan2, cudaFuncAttributeMaxDynamicSharedMemorySize, SMEM_SCAN);

    // ---- fork: CSR build on side stream, GEMM chain on main stream ----
    cudaEventRecord(s_fork, 0);
    cudaStreamWaitEvent(s_side, s_fork, 0);

    {   // CSR build (side stream)
        int nbe1 = cdiv(E_nn, T), nbe2 = cdiv(E_in, T);
        zero_deg2<<<cdiv(N_NEWS, T), T, 0, s_side>>>(deg_nn, deg_in, N_NEWS);
        hist2<<<nbe1 + nbe2, T, 0, s_side>>>(edge_nn, E_nn, deg_nn, edge_in, E_in, deg_in, nbe1);
        scan2<<<2, 1024, SMEM_SCAN, s_side>>>(deg_nn, rp_nn, cur_nn, deg_in, rp_in, cur_in, N_NEWS);
        scatter2<<<nbe1 + nbe2, T, 0, s_side>>>(edge_nn, E_nn, cur_nn, csr_nn,
                                                edge_in, E_in, cur_in, csr_in, nbe1);
        cudaEventRecord(s_join, s_side);
    }

    // ---- main stream: weight prep + projections (fp16 mma) + attention dots ----
    transpose_all<<<cdiv(128 * 384, T), T>>>(W_news, W_inter, Wk, BtNh, BtIh, BtKh, accsem);
    const int nb1 = cdiv(N_NEWS, 128), nb2 = cdiv(N_INTER, 128);
    mma_gemm_h<<<nb1 + nb2, 256, SMEM_GEMM>>>(x_news, x_inter, BtNh, BtIh, b_news, b_inter,
                                              h_news, h_inter, hh_news, hh_inter,
                                              N_NEWS, N_INTER, nb1, 768);
    {
        int nbA = cdiv(N_NEWS * NH, T), nbB = cdiv(N_INTER * NH, T);
        att_all<<<nbA + nbB, T>>>(h_news, h_inter, a_src_nn, a_dst_nn, a_dst_in, a_src_in,
                                  asrc_nn, adst_nn, adst_in, asrc_in, nbA);
    }

    // ---- join: aggregation needs CSR + h + att ----
    cudaStreamWaitEvent(0, s_join, 0);
    han_agg2<<<cdiv(2 * N_NEWS * 32, T), T>>>(rp_nn, csr_nn, asrc_nn, adst_nn, hh_news, oh_nn,
                                              rp_in, csr_in, asrc_in, adst_in, hh_inter, oh_in);

    // ---- semantic attention (fp16 mma, A pre-packed, merged dual-part) ----
    mma_gemm_hs<<<2 * nb1, 256, SMEM_GEMM>>>(oh_nn, oh_in, BtKh, bk,
                                             accsem, accsem + 128, N_NEWS, N_NEWS, nb1, 128);
    beta_kernel<<<1, 128>>>(accsem, q, beta);

    // ---- fuse + ELU + output head (fp16 inputs) ----
    final_kernel<<<cdiv(N_NEWS * 32, T), T>>>(oh_nn, oh_in, beta, W_out, b_out, y);
}

// round 17
// speedup vs baseline: 1.2320x; 1.1303x over previous
#include <cuda_runtime.h>
#include <cuda_fp16.h>
#include <math.h>
#include <stdint.h>

#define N_NEWS  30000
#define N_INTER 60000
#define HID 128
#define NH  8
#define HD  16
#define E_NN_CAP 480000
#define E_IN_CAP 960000

// ---------------- scratch (static device globals; no allocation) ----------------
__device__ uint32_t g_hh_news [N_NEWS  * 64];   // half2-packed h (gather + att)
__device__ uint32_t g_hh_inter[N_INTER * 64];
__device__ uint32_t g_oh_nn  [N_NEWS  * 64];    // half2-packed metapath outputs
__device__ uint32_t g_oh_in  [N_NEWS  * 64];
__device__ uint32_t g_BtNh   [HID * 384];       // W_news^T, half2-packed [n][k/2]
__device__ uint32_t g_BtIh   [HID * 384];       // W_inter^T, half2-packed
__device__ uint32_t g_BtKh   [HID * 64];        // Wk^T, half2-packed [n][k/2]
__device__ float    g_asrc_nn[N_NEWS  * NH];
__device__ float    g_adst_nn[N_NEWS  * NH];
__device__ float    g_asrc_in[N_INTER * NH];
__device__ float    g_adst_in[N_NEWS  * NH];
__device__ int      g_deg_nn [N_NEWS];
__device__ int      g_deg_in [N_NEWS];
__device__ int      g_rp_nn  [N_NEWS + 1];
__device__ int      g_rp_in  [N_NEWS + 1];
__device__ int      g_cur_nn [N_NEWS];
__device__ int      g_cur_in [N_NEWS];
__device__ int      g_csr_nn [E_NN_CAP];
__device__ int      g_csr_in [E_IN_CAP];
__device__ float    g_accsem[2 * HID];
__device__ float    g_beta  [2];

// ---------------- helpers ----------------
static __device__ __forceinline__ uint32_t smem_u32(const void* p) {
    uint32_t r;
    asm("{ .reg .u64 t; cvta.to.shared.u64 t, %1; cvt.u32.u64 %0, t; }" : "=r"(r) : "l"(p));
    return r;
}
static __device__ __forceinline__ void mma_f16(float* c, const uint32_t* a, const uint32_t* b) {
    asm volatile(
        "mma.sync.aligned.m16n8k16.row.col.f32.f16.f16.f32 "
        "{%0,%1,%2,%3},{%4,%5,%6,%7},{%8,%9},{%0,%1,%2,%3};"
        : "+f"(c[0]), "+f"(c[1]), "+f"(c[2]), "+f"(c[3])
        : "r"(a[0]), "r"(a[1]), "r"(a[2]), "r"(a[3]), "r"(b[0]), "r"(b[1]));
}
static __device__ __forceinline__ void cp16(uint32_t dst, const void* src) {
    asm volatile("cp.async.cg.shared.global [%0], [%1], 16;" :: "r"(dst), "l"(src));
}
static __device__ __forceinline__ void ldsm4(uint32_t* r, uint32_t addr) {
    asm volatile("ldmatrix.sync.aligned.m8n8.x4.shared.b16 {%0,%1,%2,%3}, [%4];"
                 : "=r"(r[0]), "=r"(r[1]), "=r"(r[2]), "=r"(r[3]) : "r"(addr));
}
__device__ __forceinline__ float lrelu02(float x) { return x > 0.f ? x : 0.2f * x; }
static __device__ __forceinline__ uint32_t pack_h2(float a, float b) {
    __half2 h = __floats2half2_rn(a, b);
    return *reinterpret_cast<uint32_t*>(&h);
}

// ---------------- setup: zero degree counters ----------------
__global__ void zero_deg2(int* __restrict__ d1, int* __restrict__ d2, int n) {
    int i = blockIdx.x * blockDim.x + threadIdx.x;
    if (i < n) { d1[i] = 0; d2[i] = 0; }
}

// ---------------- weight prep: fp16-pack all weights, zero accsem ----------------
__global__ void transpose_all(const float* __restrict__ Wn, const float* __restrict__ Wi,
                              const float* __restrict__ Wk,
                              uint32_t* __restrict__ BtNh, uint32_t* __restrict__ BtIh,
                              uint32_t* __restrict__ BtKh, float* __restrict__ accsem)
{
    int i = blockIdx.x * blockDim.x + threadIdx.x;
    if (i < 128 * 384) {                 // (n, k-pair)
        int n = i / 384, kp = i % 384;
        BtNh[i] = pack_h2(Wn[(2 * kp) * 128 + n], Wn[(2 * kp + 1) * 128 + n]);
        BtIh[i] = pack_h2(Wi[(2 * kp) * 128 + n], Wi[(2 * kp + 1) * 128 + n]);
    }
    if (i < 128 * 64) {
        int n = i >> 6, kp = i & 63;
        BtKh[i] = pack_h2(Wk[(2 * kp) * 128 + n], Wk[(2 * kp + 1) * 128 + n]);
    }
    if (i < 2 * HID) accsem[i] = 0.f;
}

#define LDT 36              // padded row length (32-bit words); 144B rows
#define BUF_F (128 * LDT)   // words per (A or B) tile

// ---------------- fp16 tensor-core GEMM (projection, dual-part, 2-stage) ----------------
// A fp32 in gmem -> cvt to half2 at register-prefetch -> STS; B pre-packed fp16.
// Epilogue: Hh[m][n/2] = half2(acc + bias) only (no fp32 store).
__global__ __launch_bounds__(256, 2)
void mma_gemm_h(const float* __restrict__ A1, const float* __restrict__ A2,
                const uint32_t* __restrict__ Bt1, const uint32_t* __restrict__ Bt2,
                const float* __restrict__ bias1, const float* __restrict__ bias2,
                uint32_t* __restrict__ Hh1, uint32_t* __restrict__ Hh2,
                int M1, int M2, int nb1, int K)
{
    extern __shared__ uint32_t smw[];   // [2][A + B] tiles (words)
    __shared__ float s_bias[128];

    const int tid  = threadIdx.x;
    const int warp = tid >> 5;
    const int lane = tid & 31;
    const int group = lane >> 2, tig = lane & 3;
    const int warpM = warp & 3, warpN = warp >> 2;
    const int mbase = warpM * 32, nbase = warpN * 64;

    const float* A; const uint32_t* Bt; const float* bias; uint32_t* Hh; int M, m0;
    if ((int)blockIdx.x < nb1) {
        A = A1; Bt = Bt1; bias = bias1; Hh = Hh1; M = M1; m0 = blockIdx.x * 128;
    } else {
        A = A2; Bt = Bt2; bias = bias2; Hh = Hh2; M = M2; m0 = (blockIdx.x - nb1) * 128;
    }
    const int Kw = K >> 1;              // B row length in words

    if (tid < 128) s_bias[tid] = bias[tid];

    float acc[2][8][4];
#pragma unroll
    for (int i = 0; i < 2; i++)
#pragma unroll
        for (int j = 0; j < 8; j++)
#pragma unroll
            for (int l = 0; l < 4; l++) acc[i][j][l] = 0.f;

    const int nchunk = K >> 6;          // 64 halfs per chunk
    const uint32_t smem_b = smem_u32(smw);

    const int rowL = tid >> 3, qL = tid & 7;   // qL: 32B unit within 128B row
    const int blk = lane >> 3, rr = lane & 7;
    const uint32_t offA = (uint32_t)(((mbase + (blk & 1) * 8 + rr) * LDT + (blk >> 1) * 4) * 4);
    const uint32_t offB = (uint32_t)(((nbase + (blk >> 1) * 8 + rr) * LDT + (blk & 1) * 4) * 4);

    uint4 pa[4];
    auto prefetchA = [&](int c) {
        const int kb = c * 64;
#pragma unroll
        for (int p = 0; p < 4; p++) {
            int row = rowL + 32 * p;
            int m = m0 + row;
            if (m < M) {
                const float4* src = reinterpret_cast<const float4*>(A + (size_t)m * K + kb + qL * 8);
                float4 va = src[0], vb = src[1];
                pa[p] = make_uint4(pack_h2(va.x, va.y), pack_h2(va.z, va.w),
                                   pack_h2(vb.x, vb.y), pack_h2(vb.z, vb.w));
            } else {
                pa[p] = make_uint4(0u, 0u, 0u, 0u);
            }
        }
    };
    auto issueB = [&](int c) {
        const int kbw = c * 32;
        const uint32_t bo = smem_b + ((uint32_t)(((c & 1) * 2 + 1) * BUF_F) << 2);
#pragma unroll
        for (int p = 0; p < 4; p++) {
            int row = rowL + 32 * p;
            cp16(bo + (uint32_t)((row * LDT + qL * 4) << 2),
                 Bt + (size_t)row * Kw + kbw + qL * 4);
        }
        asm volatile("cp.async.commit_group;");
    };

    prefetchA(0);
    issueB(0);

    for (int c = 0; c < nchunk; c++) {
        uint32_t* Asm = smw + (c & 1) * 2 * BUF_F;
#pragma unroll
        for (int p = 0; p < 4; p++) {
            int row = rowL + 32 * p;
            *reinterpret_cast<uint4*>(Asm + row * LDT + qL * 4) = pa[p];
        }
        if (c + 1 < nchunk) {
            issueB(c + 1);
            asm volatile("cp.async.wait_group 1;");
        } else {
            asm volatile("cp.async.wait_group 0;");
        }
        __syncthreads();
        if (c + 1 < nchunk) prefetchA(c + 1);

        const uint32_t Asb = smem_b + ((uint32_t)((c & 1) * 2 * BUF_F) << 2);
        const uint32_t Bsb = Asb + (uint32_t)(BUF_F << 2);
#pragma unroll
        for (int ks = 0; ks < 4; ks++) {
            uint32_t af[2][4], bf[8][2];
            ldsm4(af[0], Asb + offA + (uint32_t)(ks * 32));
            ldsm4(af[1], Asb + offA + (uint32_t)(16 * LDT * 4 + ks * 32));
#pragma unroll
            for (int na2 = 0; na2 < 8; na2 += 2) {
                uint32_t t[4];
                ldsm4(t, Bsb + offB + (uint32_t)(na2 * 8 * LDT * 4 + ks * 32));
                bf[na2][0] = t[0]; bf[na2][1] = t[1];
                bf[na2 + 1][0] = t[2]; bf[na2 + 1][1] = t[3];
            }
#pragma unroll
            for (int ma = 0; ma < 2; ma++)
#pragma unroll
                for (int na = 0; na < 8; na++)
                    mma_f16(acc[ma][na], af[ma], bf[na]);
        }
        __syncthreads();
    }

    // epilogue: bias + half2 pack only
#pragma unroll
    for (int ma = 0; ma < 2; ma++) {
        int row = m0 + mbase + ma * 16 + group;
#pragma unroll
        for (int na = 0; na < 8; na++) {
            int col = nbase + na * 8 + tig * 2;
            if (row < M)
                Hh[(size_t)row * 64 + (col >> 1)] =
                    pack_h2(acc[ma][na][0] + s_bias[col], acc[ma][na][1] + s_bias[col + 1]);
            if (row + 8 < M)
                Hh[(size_t)(row + 8) * 64 + (col >> 1)] =
                    pack_h2(acc[ma][na][2] + s_bias[col], acc[ma][na][3] + s_bias[col + 1]);
        }
    }
}

// ---------------- fp16 tensor-core GEMM (semantic, dual-part, A pre-packed) ----------------
__global__ __launch_bounds__(256, 2)
void mma_gemm_hs(const uint32_t* __restrict__ A1, const uint32_t* __restrict__ A2,
                 const uint32_t* __restrict__ Bt,
                 const float* __restrict__ bias,
                 float* __restrict__ C1, float* __restrict__ C2,
                 int M1, int M2, int nb1, int K)
{
    extern __shared__ uint32_t smw[];
    __shared__ float s_bias[128];
    __shared__ float s_col[128];

    const int tid  = threadIdx.x;
    const int warp = tid >> 5;
    const int lane = tid & 31;
    const int group = lane >> 2, tig = lane & 3;
    const int warpM = warp & 3, warpN = warp >> 2;
    const int mbase = warpM * 32, nbase = warpN * 64;

    const uint32_t* A; float* C; int M, m0;
    if ((int)blockIdx.x < nb1) { A = A1; C = C1; M = M1; m0 = blockIdx.x * 128; }
    else                       { A = A2; C = C2; M = M2; m0 = (blockIdx.x - nb1) * 128; }
    const int Kw = K >> 1;

    if (tid < 128) { s_bias[tid] = bias[tid]; s_col[tid] = 0.f; }

    float acc[2][8][4];
#pragma unroll
    for (int i = 0; i < 2; i++)
#pragma unroll
        for (int j = 0; j < 8; j++)
#pragma unroll
            for (int l = 0; l < 4; l++) acc[i][j][l] = 0.f;

    const int nchunk = K >> 6;          // 2 for K=128
    const uint32_t smem_b = smem_u32(smw);

    const int rowL = tid >> 3, qL = tid & 7;
    const int blk = lane >> 3, rr = lane & 7;
    const uint32_t offA = (uint32_t)(((mbase + (blk & 1) * 8 + rr) * LDT + (blk >> 1) * 4) * 4);
    const uint32_t offB = (uint32_t)(((nbase + (blk >> 1) * 8 + rr) * LDT + (blk & 1) * 4) * 4);

    auto issue_chunk = [&](int c) {
        const int kbw = c * 32;
        const uint32_t bo = smem_b + ((uint32_t)((c & 1) * 2 * BUF_F) << 2);
#pragma unroll
        for (int p = 0; p < 4; p++) {
            int row = rowL + 32 * p;
            int m = m0 + row;
            cp16(bo + (uint32_t)((row * LDT + qL * 4) << 2),
                 A + (size_t)(m < M ? m : 0) * Kw + kbw + qL * 4);
            cp16(bo + (uint32_t)((BUF_F + row * LDT + qL * 4) << 2),
                 Bt + (size_t)row * Kw + kbw + qL * 4);
        }
        asm volatile("cp.async.commit_group;");
    };

    issue_chunk(0);
    for (int c = 0; c < nchunk; c++) {
        if (c + 1 < nchunk) {
            issue_chunk(c + 1);
            asm volatile("cp.async.wait_group 1;");
        } else {
            asm volatile("cp.async.wait_group 0;");
        }
        __syncthreads();

        const uint32_t Asb = smem_b + ((uint32_t)((c & 1) * 2 * BUF_F) << 2);
        const uint32_t Bsb = Asb + (uint32_t)(BUF_F << 2);
#pragma unroll
        for (int ks = 0; ks < 4; ks++) {
            uint32_t af[2][4], bf[8][2];
            ldsm4(af[0], Asb + offA + (uint32_t)(ks * 32));
            ldsm4(af[1], Asb + offA + (uint32_t)(16 * LDT * 4 + ks * 32));
#pragma unroll
            for (int na2 = 0; na2 < 8; na2 += 2) {
                uint32_t t[4];
                ldsm4(t, Bsb + offB + (uint32_t)(na2 * 8 * LDT * 4 + ks * 32));
                bf[na2][0] = t[0]; bf[na2][1] = t[1];
                bf[na2 + 1][0] = t[2]; bf[na2 + 1][1] = t[3];
            }
#pragma unroll
            for (int ma = 0; ma < 2; ma++)
#pragma unroll
                for (int na = 0; na < 8; na++)
                    mma_f16(acc[ma][na], af[ma], bf[na]);
        }
        __syncthreads();
    }

    // semantic epilogue: column sums of tanh(acc + bias)
#pragma unroll
    for (int na = 0; na < 8; na++) {
        int col = nbase + na * 8 + tig * 2;
        float p0 = 0.f, p1 = 0.f;
#pragma unroll
        for (int ma = 0; ma < 2; ma++) {
            int row = m0 + mbase + ma * 16 + group;
            if (row < M) {
                p0 += tanhf(acc[ma][na][0] + s_bias[col]);
                p1 += tanhf(acc[ma][na][1] + s_bias[col + 1]);
            }
            if (row + 8 < M) {
                p0 += tanhf(acc[ma][na][2] + s_bias[col]);
                p1 += tanhf(acc[ma][na][3] + s_bias[col + 1]);
            }
        }
        atomicAdd(&s_col[col], p0);
        atomicAdd(&s_col[col + 1], p1);
    }
    __syncthreads();
    if (tid < 128) atomicAdd(&C[tid], s_col[tid]);
}

// ---------------- attention dots from fp16 h tables, both node types ----------------
__global__ void att_all(const uint32_t* __restrict__ hhN, const uint32_t* __restrict__ hhI,
                        const float* __restrict__ v0, const float* __restrict__ v1,
                        const float* __restrict__ v2, const float* __restrict__ v3,
                        float* __restrict__ o0, float* __restrict__ o1,
                        float* __restrict__ o2, float* __restrict__ o3, int nbA)
{
    __shared__ float sv[4][128];
    if (threadIdx.x < 128) {
        sv[0][threadIdx.x] = v0[threadIdx.x];
        sv[1][threadIdx.x] = v1[threadIdx.x];
        sv[2][threadIdx.x] = v2[threadIdx.x];
        sv[3][threadIdx.x] = v3[threadIdx.x];
    }
    __syncthreads();
    if ((int)blockIdx.x < nbA) {
        int i = blockIdx.x * blockDim.x + threadIdx.x;
        if (i < N_NEWS * NH) {
            int n = i >> 3, hh = i & 7;
            const uint4* hp = reinterpret_cast<const uint4*>(hhN + (size_t)n * 64 + hh * 8);
            uint4 w0 = hp[0], w1 = hp[1];
            const uint32_t wv[8] = { w0.x, w0.y, w0.z, w0.w, w1.x, w1.y, w1.z, w1.w };
            float s0 = 0.f, s1 = 0.f, s2 = 0.f;
#pragma unroll
            for (int p = 0; p < 8; p++) {
                float2 x = __half22float2(*reinterpret_cast<const __half2*>(&wv[p]));
                int d = p * 2;
                s0 += x.x * sv[0][hh * HD + d]     + x.y * sv[0][hh * HD + d + 1];
                s1 += x.x * sv[1][hh * HD + d]     + x.y * sv[1][hh * HD + d + 1];
                s2 += x.x * sv[2][hh * HD + d]     + x.y * sv[2][hh * HD + d + 1];
            }
            o0[i] = s0; o1[i] = s1; o2[i] = s2;
        }
    } else {
        int i = (blockIdx.x - nbA) * blockDim.x + threadIdx.x;
        if (i < N_INTER * NH) {
            int n = i >> 3, hh = i & 7;
            const uint4* hp = reinterpret_cast<const uint4*>(hhI + (size_t)n * 64 + hh * 8);
            uint4 w0 = hp[0], w1 = hp[1];
            const uint32_t wv[8] = { w0.x, w0.y, w0.z, w0.w, w1.x, w1.y, w1.z, w1.w };
            float s = 0.f;
#pragma unroll
            for (int p = 0; p < 8; p++) {
                float2 x = __half22float2(*reinterpret_cast<const __half2*>(&wv[p]));
                int d = p * 2;
                s += x.x * sv[3][hh * HD + d] + x.y * sv[3][hh * HD + d + 1];
            }
            o3[i] = s;
        }
    }
}

// ---------------- CSR build (merged dual-edge-type kernels) ----------------
__global__ void hist2(const int* __restrict__ e1, int E1, int* __restrict__ d1,
                      const int* __restrict__ e2, int E2, int* __restrict__ d2, int nb1)
{
    if ((int)blockIdx.x < nb1) {
        int e = blockIdx.x * blockDim.x + threadIdx.x;
        if (e < E1) atomicAdd(&d1[e1[E1 + e]], 1);
    } else {
        int e = (blockIdx.x - nb1) * blockDim.x + threadIdx.x;
        if (e < E2) atomicAdd(&d2[e2[E2 + e]], 1);
    }
}

__global__ __launch_bounds__(1024)
void scan2(const int* __restrict__ degA, int* __restrict__ rpA, int* __restrict__ curA,
           const int* __restrict__ degB, int* __restrict__ rpB, int* __restrict__ curB,
           int n)
{
    extern __shared__ int sdeg[];
    __shared__ int wsum[32];
    const int* deg = blockIdx.x ? degB : degA;
    int* rowptr    = blockIdx.x ? rpB  : rpA;
    int* cursor    = blockIdx.x ? curB : curA;

    const int t = threadIdx.x, lane = t & 31, wid = t >> 5;
    const int chunk = (n + 1023) >> 10;
    const int b = t * chunk;

    for (int i = t; i < n; i += 1024) sdeg[i] = deg[i];
    __syncthreads();

    int v[32];
    int sum = 0;
#pragma unroll
    for (int i = 0; i < 32; i++) {
        if (i < chunk) {
            int idx = b + i;
            int x = (idx < n) ? sdeg[idx] : 0;
            v[i] = sum;
            sum += x;
        }
    }
    int inc = sum;
#pragma unroll
    for (int off = 1; off < 32; off <<= 1) {
        int y = __shfl_up_sync(0xffffffffu, inc, off);
        if (lane >= off) inc += y;
    }
    if (lane == 31) wsum[wid] = inc;
    __syncthreads();
    if (wid == 0) {
        int ws = wsum[lane];
        int winc = ws;
#pragma unroll
        for (int off = 1; off < 32; off <<= 1) {
            int y = __shfl_up_sync(0xffffffffu, winc, off);
            if (lane >= off) winc += y;
        }
        wsum[lane] = winc - ws;
    }
    __syncthreads();
    const int base = wsum[wid] + (inc - sum);
#pragma unroll
    for (int i = 0; i < 32; i++) {
        if (i < chunk) {
            int idx = b + i;
            if (idx < n) sdeg[idx] = base + v[i];
        }
    }
    __syncthreads();
    for (int i = t; i < n; i += 1024) {
        int val = sdeg[i];
        rowptr[i] = val;
        cursor[i] = val;
    }
    if (t == 1023) rowptr[n] = base + sum;
}

__global__ void scatter2(const int* __restrict__ e1, int E1, int* __restrict__ c1, int* __restrict__ s1,
                         const int* __restrict__ e2, int E2, int* __restrict__ c2, int* __restrict__ s2,
                         int nb1)
{
    if ((int)blockIdx.x < nb1) {
        int e = blockIdx.x * blockDim.x + threadIdx.x;
        if (e < E1) { int pos = atomicAdd(&c1[e1[E1 + e]], 1); s1[pos] = e1[e]; }
    } else {
        int e = (blockIdx.x - nb1) * blockDim.x + threadIdx.x;
        if (e < E2) { int pos = atomicAdd(&c2[e2[E2 + e]], 1); s2[pos] = e2[e]; }
    }
}

// ---------------- fused single-pass softmax-aggregation: warp per dst node ----------------
__global__ __launch_bounds__(256)
void han_agg2(const int* __restrict__ rp1, const int* __restrict__ csr1,
              const float* __restrict__ as1, const float* __restrict__ ad1,
              const uint32_t* __restrict__ hh1, uint32_t* __restrict__ o1,
              const int* __restrict__ rp2, const int* __restrict__ csr2,
              const float* __restrict__ as2, const float* __restrict__ ad2,
              const uint32_t* __restrict__ hh2, uint32_t* __restrict__ o2)
{
    int gtid = blockIdx.x * blockDim.x + threadIdx.x;
    int w = gtid >> 5;
    int lane = threadIdx.x & 31;

    const int* rowptr; const int* csr; const float* asrc; const float* adst;
    const uint32_t* hh; uint32_t* out; int d;
    if (w < N_NEWS) {
        d = w; rowptr = rp1; csr = csr1; asrc = as1; adst = ad1; hh = hh1; out = o1;
    } else if (w < 2 * N_NEWS) {
        d = w - N_NEWS; rowptr = rp2; csr = csr2; asrc = as2; adst = ad2; hh = hh2; out = o2;
    } else return;

    const int beg = rowptr[d], end = rowptr[d + 1];
    const int deg = end - beg;
    uint2* o = reinterpret_cast<uint2*>(out) + (size_t)d * 32 + lane;
    if (deg == 0) { *o = make_uint2(0u, 0u); return; }

    const int hdid = lane >> 2;
    const float adh = adst[(size_t)d * 8 + hdid];
    const uint2* h2p = reinterpret_cast<const uint2*>(hh);

    float den = 0.f, a0 = 0.f, a1 = 0.f, a2 = 0.f, a3 = 0.f;
    int i = 0;
    for (; i + 4 <= deg; i += 4) {
        int sA = csr[beg + i],     sB = csr[beg + i + 1];
        int sC = csr[beg + i + 2], sD = csr[beg + i + 3];
        float avA = asrc[(size_t)sA * 8 + hdid];
        float avB = asrc[(size_t)sB * 8 + hdid];
        float avC = asrc[(size_t)sC * 8 + hdid];
        float avD = asrc[(size_t)sD * 8 + hdid];
        uint2 gA = h2p[(size_t)sA * 32 + lane];
        uint2 gB = h2p[(size_t)sB * 32 + lane];
        uint2 gC = h2p[(size_t)sC * 32 + lane];
        uint2 gD = h2p[(size_t)sD * 32 + lane];
        float wA = __expf(lrelu02(avA + adh));
        float wB = __expf(lrelu02(avB + adh));
        float wC = __expf(lrelu02(avC + adh));
        float wD = __expf(lrelu02(avD + adh));
        den += (wA + wB) + (wC + wD);
        float2 lA0 = __half22float2(*reinterpret_cast<__half2*>(&gA.x));
        float2 lA1 = __half22float2(*reinterpret_cast<__half2*>(&gA.y));
        float2 lB0 = __half22float2(*reinterpret_cast<__half2*>(&gB.x));
        float2 lB1 = __half22float2(*reinterpret_cast<__half2*>(&gB.y));
        float2 lC0 = __half22float2(*reinterpret_cast<__half2*>(&gC.x));
        float2 lC1 = __half22float2(*reinterpret_cast<__half2*>(&gC.y));
        float2 lD0 = __half22float2(*reinterpret_cast<__half2*>(&gD.x));
        float2 lD1 = __half22float2(*reinterpret_cast<__half2*>(&gD.y));
        a0 += lA0.x * wA + lB0.x * wB + lC0.x * wC + lD0.x * wD;
        a1 += lA0.y * wA + lB0.y * wB + lC0.y * wC + lD0.y * wD;
        a2 += lA1.x * wA + lB1.x * wB + lC1.x * wC + lD1.x * wD;
        a3 += lA1.y * wA + lB1.y * wB + lC1.y * wC + lD1.y * wD;
    }
    for (; i < deg; i++) {
        int s = csr[beg + i];
        float av = asrc[(size_t)s * 8 + hdid];
        uint2 g = h2p[(size_t)s * 32 + lane];
        float wgt = __expf(lrelu02(av + adh));
        den += wgt;
        float2 l0 = __half22float2(*reinterpret_cast<__half2*>(&g.x));
        float2 l1 = __half22float2(*reinterpret_cast<__half2*>(&g.y));
        a0 += l0.x * wgt; a1 += l0.y * wgt;
        a2 += l1.x * wgt; a3 += l1.y * wgt;
    }
    float invd = 1.f / (den + 1e-16f);
    *o = make_uint2(pack_h2(fmaxf(a0 * invd, 0.f), fmaxf(a1 * invd, 0.f)),
                    pack_h2(fmaxf(a2 * invd, 0.f), fmaxf(a3 * invd, 0.f)));
}

// ---------------- semantic softmax beta ----------------
__global__ void beta_kernel(const float* __restrict__ acc, const float* __restrict__ q,
                            float* __restrict__ beta)
{
    __shared__ float red[2][4];
    int t = threadIdx.x;  // 128 threads
    float s0 = q[t] * acc[t]       * (1.f / N_NEWS);
    float s1 = q[t] * acc[128 + t] * (1.f / N_NEWS);
#pragma unroll
    for (int off = 16; off; off >>= 1) {
        s0 += __shfl_down_sync(0xffffffffu, s0, off);
        s1 += __shfl_down_sync(0xffffffffu, s1, off);
    }
    if ((t & 31) == 0) { red[0][t >> 5] = s0; red[1][t >> 5] = s1; }
    __syncthreads();
    if (t == 0) {
        float sc0 = red[0][0] + red[0][1] + red[0][2] + red[0][3];
        float sc1 = red[1][0] + red[1][1] + red[1][2] + red[1][3];
        float mx = fmaxf(sc0, sc1);
        float e0 = __expf(sc0 - mx), e1 = __expf(sc1 - mx);
        float inv = 1.f / (e0 + e1);
        beta[0] = e0 * inv;
        beta[1] = e1 * inv;
    }
}

// ---------------- final: fuse + ELU + [128x4] head (warp per node, fp16 inputs) ----------------
__global__ void final_kernel(const uint32_t* __restrict__ onn, const uint32_t* __restrict__ oin,
                             const float* __restrict__ beta, const float* __restrict__ Wout,
                             const float* __restrict__ bout, float* __restrict__ y)
{
    __shared__ float sw[HID * 4];
    for (int i = threadIdx.x; i < HID * 4; i += blockDim.x) sw[i] = Wout[i];
    __syncthreads();

    int gtid = blockIdx.x * blockDim.x + threadIdx.x;
    int node = gtid >> 5;
    int lane = threadIdx.x & 31;
    if (node >= N_NEWS) return;

    float b0 = beta[0], b1 = beta[1];
    uint2 ga = reinterpret_cast<const uint2*>(onn)[(size_t)node * 32 + lane];
    uint2 gb = reinterpret_cast<const uint2*>(oin)[(size_t)node * 32 + lane];
    float2 a0 = __half22float2(*reinterpret_cast<__half2*>(&ga.x));
    float2 a1 = __half22float2(*reinterpret_cast<__half2*>(&ga.y));
    float2 c0 = __half22float2(*reinterpret_cast<__half2*>(&gb.x));
    float2 c1 = __half22float2(*reinterpret_cast<__half2*>(&gb.y));
    float f[4] = { b0 * a0.x + b1 * c0.x, b0 * a0.y + b1 * c0.y,
                   b0 * a1.x + b1 * c1.x, b0 * a1.y + b1 * c1.y };   // inputs already relu'd
#pragma unroll
    for (int u = 0; u < 4; u++) f[u] = f[u] > 0.f ? f[u] : (__expf(f[u]) - 1.f);

    float p[4] = { 0.f, 0.f, 0.f, 0.f };
#pragma unroll
    for (int u = 0; u < 4; u++) {
        int r = lane * 4 + u;
#pragma unroll
        for (int c = 0; c < 4; c++) p[c] += f[u] * sw[r * 4 + c];
    }
#pragma unroll
    for (int off = 16; off; off >>= 1)
#pragma unroll
        for (int c = 0; c < 4; c++) p[c] += __shfl_down_sync(0xffffffffu, p[c], off);
    if (lane == 0) {
#pragma unroll
        for (int c = 0; c < 4; c++) y[(size_t)node * 4 + c] = p[c] + bout[c];
    }
}

// ---------------- host ----------------
static inline int cdiv(int a, int b) { return (a + b - 1) / b; }

extern "C" void kernel_launch(void* const* d_in, const int* in_sizes, int n_in,
                              void* d_out, int out_size)
{
    const float* x_news   = (const float*)d_in[0];
    const float* x_inter  = (const float*)d_in[1];
    const int*   edge_nn  = (const int*)  d_in[2];
    const int*   edge_in  = (const int*)  d_in[3];
    const float* W_news   = (const float*)d_in[4];
    const float* b_news   = (const float*)d_in[5];
    const float* W_inter  = (const float*)d_in[6];
    const float* b_inter  = (const float*)d_in[7];
    const float* a_src_nn = (const float*)d_in[8];
    const float* a_dst_nn = (const float*)d_in[9];
    const float* a_src_in = (const float*)d_in[10];
    const float* a_dst_in = (const float*)d_in[11];
    const float* Wk       = (const float*)d_in[12];
    const float* bk       = (const float*)d_in[13];
    const float* q        = (const float*)d_in[14];
    const float* W_out    = (const float*)d_in[15];
    const float* b_out    = (const float*)d_in[16];
    float* y = (float*)d_out;

    const int E_nn = in_sizes[2] / 2;
    const int E_in = in_sizes[3] / 2;

    float *asrc_nn, *adst_nn, *asrc_in, *adst_in, *accsem, *beta;
    uint32_t *hh_news, *hh_inter, *oh_nn, *oh_in, *BtNh, *BtIh, *BtKh;
    int *deg_nn, *deg_in, *rp_nn, *rp_in, *cur_nn, *cur_in, *csr_nn, *csr_in;
    cudaGetSymbolAddress((void**)&hh_news, g_hh_news);
    cudaGetSymbolAddress((void**)&hh_inter,g_hh_inter);
    cudaGetSymbolAddress((void**)&oh_nn,   g_oh_nn);
    cudaGetSymbolAddress((void**)&oh_in,   g_oh_in);
    cudaGetSymbolAddress((void**)&BtNh,    g_BtNh);
    cudaGetSymbolAddress((void**)&BtIh,    g_BtIh);
    cudaGetSymbolAddress((void**)&BtKh,    g_BtKh);
    cudaGetSymbolAddress((void**)&asrc_nn, g_asrc_nn);
    cudaGetSymbolAddress((void**)&adst_nn, g_adst_nn);
    cudaGetSymbolAddress((void**)&asrc_in, g_asrc_in);
    cudaGetSymbolAddress((void**)&adst_in, g_adst_in);
    cudaGetSymbolAddress((void**)&deg_nn,  g_deg_nn);
    cudaGetSymbolAddress((void**)&deg_in,  g_deg_in);
    cudaGetSymbolAddress((void**)&rp_nn,   g_rp_nn);
    cudaGetSymbolAddress((void**)&rp_in,   g_rp_in);
    cudaGetSymbolAddress((void**)&cur_nn,  g_cur_nn);
    cudaGetSymbolAddress((void**)&cur_in,  g_cur_in);
    cudaGetSymbolAddress((void**)&csr_nn,  g_csr_nn);
    cudaGetSymbolAddress((void**)&csr_in,  g_csr_in);
    cudaGetSymbolAddress((void**)&accsem,  g_accsem);
    cudaGetSymbolAddress((void**)&beta,    g_beta);

    // lazy one-time side stream + fork/join events
    static cudaStream_t s_side = nullptr;
    static cudaEvent_t  s_fork = nullptr, s_join = nullptr;
    if (!s_side) {
        cudaStreamCreateWithFlags(&s_side, cudaStreamNonBlocking);
        cudaEventCreateWithFlags(&s_fork, cudaEventDisableTiming);
        cudaEventCreateWithFlags(&s_join, cudaEventDisableTiming);
    }

    const int T = 256;
    const int SMEM_GEMM = 2 * 2 * BUF_F * 4;   // 73728 bytes (2 CTA/SM)
    const int SMEM_SCAN = N_NEWS * 4;          // 120000 bytes
    cudaFuncSetAttribute(mma_gemm_h,  cudaFuncAttributeMaxDynamicSharedMemorySize, SMEM_GEMM);
    cudaFuncSetAttribute(mma_gemm_hs, cudaFuncAttributeMaxDynamicSharedMemorySize, SMEM_GEMM);
    cudaFuncSetAttribute(scan2, cudaFuncAttributeMaxDynamicSharedMemorySize, SMEM_SCAN);

    // ---- fork: CSR build on side stream, GEMM chain on main stream ----
    cudaEventRecord(s_fork, 0);
    cudaStreamWaitEvent(s_side, s_fork, 0);

    {   // CSR build (side stream)
        int nbe1 = cdiv(E_nn, T), nbe2 = cdiv(E_in, T);
        zero_deg2<<<cdiv(N_NEWS, T), T, 0, s_side>>>(deg_nn, deg_in, N_NEWS);
        hist2<<<nbe1 + nbe2, T, 0, s_side>>>(edge_nn, E_nn, deg_nn, edge_in, E_in, deg_in, nbe1);
        scan2<<<2, 1024, SMEM_SCAN, s_side>>>(deg_nn, rp_nn, cur_nn, deg_in, rp_in, cur_in, N_NEWS);
        scatter2<<<nbe1 + nbe2, T, 0, s_side>>>(edge_nn, E_nn, cur_nn, csr_nn,
                                                edge_in, E_in, cur_in, csr_in, nbe1);
        cudaEventRecord(s_join, s_side);
    }

    // ---- main stream: weight prep + projections (fp16 mma) + attention dots ----
    transpose_all<<<cdiv(128 * 384, T), T>>>(W_news, W_inter, Wk, BtNh, BtIh, BtKh, accsem);
    const int nb1 = cdiv(N_NEWS, 128), nb2 = cdiv(N_INTER, 128);
    mma_gemm_h<<<nb1 + nb2, 256, SMEM_GEMM>>>(x_news, x_inter, BtNh, BtIh, b_news, b_inter,
                                              hh_news, hh_inter, N_NEWS, N_INTER, nb1, 768);
    {
        int nbA = cdiv(N_NEWS * NH, T), nbB = cdiv(N_INTER * NH, T);
        att_all<<<nbA + nbB, T>>>(hh_news, hh_inter, a_src_nn, a_dst_nn, a_dst_in, a_src_in,
                                  asrc_nn, adst_nn, adst_in, asrc_in, nbA);
    }

    // ---- join: aggregation needs CSR + h + att ----
    cudaStreamWaitEvent(0, s_join, 0);
    han_agg2<<<cdiv(2 * N_NEWS * 32, T), T>>>(rp_nn, csr_nn, asrc_nn, adst_nn, hh_news, oh_nn,
                                              rp_in, csr_in, asrc_in, adst_in, hh_inter, oh_in);

    // ---- semantic attention (fp16 mma, A pre-packed, merged dual-part) ----
    mma_gemm_hs<<<2 * nb1, 256, SMEM_GEMM>>>(oh_nn, oh_in, BtKh, bk,
                                             accsem, accsem + 128, N_NEWS, N_NEWS, nb1, 128);
    beta_kernel<<<1, 128>>>(accsem, q, beta);

    // ---- fuse + ELU + output head (fp16 inputs) ----
    final_kernel<<<cdiv(N_NEWS * 32, T), T>>>(oh_nn, oh_in, beta, W_out, b_out, y);
}